// round 11
// baseline (speedup 1.0000x reference)
#include <cuda_runtime.h>
#include <cuda_fp16.h>
#include <cstdint>

// Problem constants (shapes are fixed by the dataset)
#define MAXN 100000
#define MAXE 1600000
#define HDIM 64
#define SCAN_B 1024

// ---------------- scratch (no allocations allowed -> __device__ globals) ----
__device__ int    g_deg[MAXN];                 // zero at load; re-zeroed by scanA
__device__ float  g_dinv[MAXN];
__device__ int    g_rowstart[MAXN + 1];
__device__ int    g_cursor[MAXN];
__device__ int    g_esrc[MAXE];
__device__ int    g_blocksum[1024];
__device__ __half g_hsA[(size_t)MAXN * HDIM];  // fp16 hs, buffer A
__device__ __half g_hsB[(size_t)MAXN * HDIM];  // fp16 hs, buffer B

// ---------------- helpers ----------------------------------------------------
__device__ __forceinline__ unsigned long long pack2(float x, float y) {
    unsigned long long r;
    asm("mov.b64 %0, {%1,%2};" : "=l"(r) : "f"(x), "f"(y));
    return r;
}
__device__ __forceinline__ unsigned long long add2(unsigned long long a,
                                                   unsigned long long b) {
    unsigned long long d;
    asm("add.rn.f32x2 %0, %1, %2;" : "=l"(d) : "l"(a), "l"(b));
    return d;
}
__device__ __forceinline__ float2 unpack2(unsigned long long v) {
    float2 f;
    asm("mov.b64 {%0,%1}, %2;" : "=f"(f.x), "=f"(f.y) : "l"(v));
    return f;
}
__device__ __forceinline__ unsigned f2tf32(float x) {
    unsigned r;
    asm("cvt.rna.tf32.f32 %0, %1;" : "=r"(r) : "f"(x));
    return r;
}
__device__ __forceinline__ void mma_tf32(float& c0, float& c1, float& c2, float& c3,
                                         unsigned a0, unsigned a1, unsigned a2,
                                         unsigned a3, unsigned b0, unsigned b1) {
    asm("mma.sync.aligned.m16n8k8.row.col.f32.tf32.tf32.f32 "
        "{%0,%1,%2,%3}, {%4,%5,%6,%7}, {%8,%9}, {%0,%1,%2,%3};"
        : "+f"(c0), "+f"(c1), "+f"(c2), "+f"(c3)
        : "r"(a0), "r"(a1), "r"(a2), "r"(a3), "r"(b0), "r"(b1));
}
// add 4 fp16 values (one u64) into 2 packed-f32x2 accumulators
__device__ __forceinline__ void acc_h4(unsigned long long v,
                                       unsigned long long& a01,
                                       unsigned long long& a23) {
    const unsigned lo = (unsigned)v, hi = (unsigned)(v >> 32);
    const float2 f0 = __half22float2(*reinterpret_cast<const __half2*>(&lo));
    const float2 f1 = __half22float2(*reinterpret_cast<const __half2*>(&hi));
    a01 = add2(a01, pack2(f0.x, f0.y));
    a23 = add2(a23, pack2(f1.x, f1.y));
}

// ---------------- CSR build --------------------------------------------------
__global__ void count_deg_kernel(const int* __restrict__ dst, int e) {
    int i = blockIdx.x * blockDim.x + threadIdx.x;
    if (i < e) atomicAdd(&g_deg[dst[i]], 1);
}

// Phase A: per-block exclusive scan of g_deg; fused dinv; re-zero deg.
__global__ void __launch_bounds__(SCAN_B)
scanA_kernel(int n) {
    __shared__ int sh[SCAN_B];
    const int t = threadIdx.x;
    const int i = blockIdx.x * SCAN_B + t;
    const int v = (i < n) ? g_deg[i] : 0;
    if (i < n) {
        g_dinv[i] = rsqrtf((float)v + 1.0f);
        g_deg[i] = 0;                       // ready for next replay
    }
    sh[t] = v;
    __syncthreads();
    int acc = v;
#pragma unroll
    for (int off = 1; off < SCAN_B; off <<= 1) {
        int u = (t >= off) ? sh[t - off] : 0;
        __syncthreads();
        acc += u;
        sh[t] = acc;
        __syncthreads();
    }
    if (i < n) g_rowstart[i] = acc - v;     // local exclusive
    if (t == SCAN_B - 1) g_blocksum[blockIdx.x] = acc;
}

// Phase C (with folded block-offset scan): each block warp-reduces the
// prefix of blocksums itself, then writes rowstart and cursor (+sentinel).
__global__ void __launch_bounds__(SCAN_B)
scanC_kernel(int n, int e) {
    __shared__ int s_off;
    const int t = threadIdx.x;
    const int bid = blockIdx.x;
    if (t < 32) {
        int s = 0;
        for (int j = t; j < bid; j += 32) s += g_blocksum[j];  // <= 4 iters
#pragma unroll
        for (int o = 16; o > 0; o >>= 1)
            s += __shfl_xor_sync(0xffffffffu, s, o);
        if (t == 0) s_off = s;
    }
    __syncthreads();
    const int i = bid * SCAN_B + t;
    if (i < n) {
        const int r = g_rowstart[i] + s_off;
        g_rowstart[i] = r;
        g_cursor[i]   = r;
    }
    if (i == 0) g_rowstart[n] = e;
}

__global__ void place_kernel(const int* __restrict__ src,
                             const int* __restrict__ dst, int e) {
    int i = blockIdx.x * blockDim.x + threadIdx.x;
    if (i < e) {
        int d = dst[i];
        int pos = atomicAdd(&g_cursor[d], 1);
        g_esrc[pos] = src[i];
    }
}

// ---------------- gather core (warp, one node) -> 4 post-GELU floats --------
// lane layout: h = lane>>4 (edge of pair), q = lane&15 (cols 4q..4q+3).
// Returns u0..u3 for this lane's q-block (both halves hold identical values).
__device__ __forceinline__ void gather_node(const __half* __restrict__ hsin,
                                            int node, int lane, int h, int q,
                                            const float* __restrict__ b,
                                            const float* __restrict__ g,
                                            const float* __restrict__ be,
                                            float& u0, float& u1,
                                            float& u2, float& u3) {
    const int s0 = g_rowstart[node];
    const int s1 = g_rowstart[node + 1];
    const unsigned long long* hsp = (const unsigned long long*)hsin;  // 16/row

    unsigned long long aA01 = 0ull, aA23 = 0ull;
    unsigned long long aB01 = 0ull, aB23 = 0ull;

    for (int e = s0; e < s1; e += 32) {
        const int cnt = min(32, s1 - e);
        const int s = (lane < cnt) ? __ldg(&g_esrc[e + lane]) : 0;
        int i = 0;
        for (; i + 4 <= cnt; i += 4) {           // 2 pairs = 4 edges per iter
            const int sa = __shfl_sync(0xffffffffu, s, i + h);
            const int sb = __shfl_sync(0xffffffffu, s, i + 2 + h);
            const unsigned long long va = __ldg(&hsp[(size_t)sa * 16 + q]);
            const unsigned long long vb = __ldg(&hsp[(size_t)sb * 16 + q]);
            acc_h4(va, aA01, aA23);
            acc_h4(vb, aB01, aB23);
        }
        for (; i < cnt; i += 2) {                // pair tail
            const int idx = i + h;
            const int sa = __shfl_sync(0xffffffffu, s, idx & 31);
            if (idx < cnt)
                acc_h4(__ldg(&hsp[(size_t)sa * 16 + q]), aA01, aA23);
        }
    }

    if (h == 0)                                  // self-loop term, once
        acc_h4(__ldg(&hsp[(size_t)node * 16 + q]), aA01, aA23);

    aA01 = add2(aA01, aB01);
    aA23 = add2(aA23, aB23);
    const float2 p01 = unpack2(aA01);
    const float2 p23 = unpack2(aA23);
    float4 acc = make_float4(p01.x, p01.y, p23.x, p23.y);
    acc.x += __shfl_xor_sync(0xffffffffu, acc.x, 16);
    acc.y += __shfl_xor_sync(0xffffffffu, acc.y, 16);
    acc.z += __shfl_xor_sync(0xffffffffu, acc.z, 16);
    acc.w += __shfl_xor_sync(0xffffffffu, acc.w, 16);

    const float dv = g_dinv[node];
    const float4 b4 = __ldg(&((const float4*)b)[q]);
    float v0 = dv * acc.x + b4.x;
    float v1 = dv * acc.y + b4.y;
    float v2 = dv * acc.z + b4.z;
    float v3 = dv * acc.w + b4.w;

    // LayerNorm over 64 values
    float s  = v0 + v1 + v2 + v3;
    float sq = v0 * v0 + v1 * v1 + v2 * v2 + v3 * v3;
#pragma unroll
    for (int o = 8; o > 0; o >>= 1) {
        s  += __shfl_xor_sync(0xffffffffu, s, o);
        sq += __shfl_xor_sync(0xffffffffu, sq, o);
    }
    const float mu   = s * (1.0f / 64.0f);
    const float var  = sq * (1.0f / 64.0f) - mu * mu;
    const float rstd = rsqrtf(var + 1e-5f);

    const float4 g4  = __ldg(&((const float4*)g)[q]);
    const float4 be4 = __ldg(&((const float4*)be)[q]);
    u0 = (v0 - mu) * rstd * g4.x + be4.x;
    u1 = (v1 - mu) * rstd * g4.y + be4.y;
    u2 = (v2 - mu) * rstd * g4.z + be4.z;
    u3 = (v3 - mu) * rstd * g4.w + be4.w;

    const float k = 0.70710678118654752f;
    u0 = 0.5f * u0 * (1.0f + erff(u0 * k));
    u1 = 0.5f * u1 * (1.0f + erff(u1 * k));
    u2 = 0.5f * u2 * (1.0f + erff(u2 * k));
    u3 = 0.5f * u3 * (1.0f + erff(u3 * k));
}

// ---------------- fused: gather+LN+GELU -> smem tf32 -> MMA W -> fp16 hsout --
// Block = 256 thr / 8 warps / 64 nodes (8 per warp). Double-buffered hs.
__global__ void __launch_bounds__(256)
fused_gather_gemm_kernel(const __half* __restrict__ hsin,
                         const float* __restrict__ b, const float* __restrict__ g,
                         const float* __restrict__ be, const float* __restrict__ Wn,
                         __half* __restrict__ hsout, int n) {
    constexpr int S = HDIM + 4;                  // padded stride (tf32 words)
    __shared__ unsigned Ys[64 * S];              // post-GELU rows (tf32)
    __shared__ unsigned Ws[HDIM * S];            // next-layer W (tf32)

    const int tid  = threadIdx.x;
    const int rb   = blockIdx.x * 64;
    const int warp = tid >> 5;
    const int lane = tid & 31;

    // Stage W (tf32)
    const float4* W4 = (const float4*)Wn;
    for (int idx = tid; idx < HDIM * (HDIM / 4); idx += 256) {
        const int k  = idx / (HDIM / 4);
        const int c4 = idx % (HDIM / 4);
        const float4 v = __ldg(&W4[(size_t)k * (HDIM / 4) + c4]);
        unsigned* d = Ws + k * S + c4 * 4;
        d[0] = f2tf32(v.x); d[1] = f2tf32(v.y);
        d[2] = f2tf32(v.z); d[3] = f2tf32(v.w);
    }

    // Gather phase: warp w handles nodes rb + w*8 .. rb + w*8 + 7
    {
        const int h = lane >> 4;
        const int q = lane & 15;
#pragma unroll 1
        for (int j = 0; j < 8; j++) {
            const int lrow = warp * 8 + j;
            const int node = rb + lrow;
            if (node < n) {
                float u0, u1, u2, u3;
                gather_node(hsin, node, lane, h, q, b, g, be, u0, u1, u2, u3);
                if (h == 0) {
                    unsigned* d = Ys + lrow * S + q * 4;
                    d[0] = f2tf32(u0); d[1] = f2tf32(u1);
                    d[2] = f2tf32(u2); d[3] = f2tf32(u3);
                }
            } else if (h == 0) {
                unsigned* d = Ys + lrow * S + q * 4;
                d[0] = 0u; d[1] = 0u; d[2] = 0u; d[3] = 0u;
            }
        }
    }
    __syncthreads();

    // MMA phase: warp w -> row-group rg = w>>1 (16 rows), col-half ch = w&1
    {
        const int rg = warp >> 1;
        const int ch = warp & 1;
        const int gg = lane >> 2;
        const int t  = lane & 3;

        float c[4][4];
#pragma unroll
        for (int i = 0; i < 4; i++)
#pragma unroll
            for (int j = 0; j < 4; j++) c[i][j] = 0.f;

        const unsigned* Yw = Ys + (rg * 16) * S;
#pragma unroll
        for (int ks = 0; ks < HDIM / 8; ks++) {
            const int kb = ks * 8;
            const unsigned a0 = Yw[gg * S + kb + t];
            const unsigned a1 = Yw[(gg + 8) * S + kb + t];
            const unsigned a2 = Yw[gg * S + kb + t + 4];
            const unsigned a3 = Yw[(gg + 8) * S + kb + t + 4];
#pragma unroll
            for (int nti = 0; nti < 4; nti++) {
                const int nt = ch * 4 + nti;
                const unsigned b0 = Ws[(kb + t) * S + nt * 8 + gg];
                const unsigned b1 = Ws[(kb + t + 4) * S + nt * 8 + gg];
                mma_tf32(c[nti][0], c[nti][1], c[nti][2], c[nti][3],
                         a0, a1, a2, a3, b0, b1);
            }
        }

        const int r0 = rb + rg * 16 + gg;
        const int r1 = r0 + 8;
        const float d0 = __ldg(&g_dinv[min(r0, n - 1)]);
        const float d1 = __ldg(&g_dinv[min(r1, n - 1)]);
        __half2* hs2 = (__half2*)hsout;          // 32 half2 per row
#pragma unroll
        for (int nti = 0; nti < 4; nti++) {
            const int nt = ch * 4 + nti;
            const int cc = nt * 4 + t;
            if (r0 < n)
                hs2[(size_t)r0 * 32 + cc] =
                    __floats2half2_rn(c[nti][0] * d0, c[nti][1] * d0);
            if (r1 < n)
                hs2[(size_t)r1 * 32 + cc] =
                    __floats2half2_rn(c[nti][2] * d1, c[nti][3] * d1);
        }
    }
}

// ---------------- final gather + head: out[node] = gelu(ln(agg)) @ Wh + bh ---
__global__ void __launch_bounds__(256)
gather_head_kernel(const __half* __restrict__ hsin,
                   const float* __restrict__ b, const float* __restrict__ g,
                   const float* __restrict__ be, const float* __restrict__ Wh,
                   const float* __restrict__ bh, float* __restrict__ out, int n) {
    const int warp = (blockIdx.x * blockDim.x + threadIdx.x) >> 5;
    const int lane = threadIdx.x & 31;
    if (warp >= n) return;
    const int h = lane >> 4;
    const int q = lane & 15;

    float u0, u1, u2, u3;
    gather_node(hsin, warp, lane, h, q, b, g, be, u0, u1, u2, u3);

    const float4 w4 = __ldg(&((const float4*)Wh)[q]);
    float p = u0 * w4.x + u1 * w4.y + u2 * w4.z + u3 * w4.w;
#pragma unroll
    for (int o = 8; o > 0; o >>= 1) p += __shfl_xor_sync(0xffffffffu, p, o);
    if (lane == 0) out[warp] = p + __ldg(&bh[0]);
}

// ---------------- layer-1 GEMM (tensor cores): hsA = fp16((X @ W1) * dinv) --
template <int KDIM>
__global__ void __launch_bounds__(128)
gemm_tf32_kernel(const float* __restrict__ X, const float* __restrict__ W, int n) {
    constexpr int SX = KDIM + 4;
    constexpr int SW = HDIM + 4;
    extern __shared__ unsigned sm[];
    unsigned* Xs = sm;
    unsigned* Ws = sm + 64 * SX;

    const int tid = threadIdx.x;
    const int rb  = blockIdx.x * 64;

    const float4* X4 = (const float4*)X;
    for (int idx = tid; idx < 64 * (KDIM / 4); idx += 128) {
        const int row = idx / (KDIM / 4);
        const int c4  = idx % (KDIM / 4);
        const int gr  = min(rb + row, n - 1);
        const float4 v = X4[(size_t)gr * (KDIM / 4) + c4];
        unsigned* d = Xs + row * SX + c4 * 4;
        d[0] = f2tf32(v.x); d[1] = f2tf32(v.y);
        d[2] = f2tf32(v.z); d[3] = f2tf32(v.w);
    }
    const float4* W4 = (const float4*)W;
    for (int idx = tid; idx < KDIM * (HDIM / 4); idx += 128) {
        const int k  = idx / (HDIM / 4);
        const int c4 = idx % (HDIM / 4);
        const float4 v = W4[(size_t)k * (HDIM / 4) + c4];
        unsigned* d = Ws + k * SW + c4 * 4;
        d[0] = f2tf32(v.x); d[1] = f2tf32(v.y);
        d[2] = f2tf32(v.z); d[3] = f2tf32(v.w);
    }
    __syncthreads();

    const int warp = tid >> 5;
    const int lane = tid & 31;
    const int g = lane >> 2;
    const int t = lane & 3;
    const unsigned* Xw = Xs + (warp * 16) * SX;

    float c[8][4];
#pragma unroll
    for (int nt = 0; nt < 8; nt++)
#pragma unroll
        for (int j = 0; j < 4; j++) c[nt][j] = 0.f;

#pragma unroll
    for (int ks = 0; ks < KDIM / 8; ks++) {
        const int kb = ks * 8;
        const unsigned a0 = Xw[g * SX + kb + t];
        const unsigned a1 = Xw[(g + 8) * SX + kb + t];
        const unsigned a2 = Xw[g * SX + kb + t + 4];
        const unsigned a3 = Xw[(g + 8) * SX + kb + t + 4];
#pragma unroll
        for (int nt = 0; nt < 8; nt++) {
            const unsigned b0 = Ws[(kb + t) * SW + nt * 8 + g];
            const unsigned b1 = Ws[(kb + t + 4) * SW + nt * 8 + g];
            mma_tf32(c[nt][0], c[nt][1], c[nt][2], c[nt][3],
                     a0, a1, a2, a3, b0, b1);
        }
    }

    const int r0 = rb + warp * 16 + g;
    const int r1 = r0 + 8;
    const float d0 = __ldg(&g_dinv[min(r0, n - 1)]);
    const float d1 = __ldg(&g_dinv[min(r1, n - 1)]);
    __half2* hs2 = (__half2*)g_hsA;
#pragma unroll
    for (int nt = 0; nt < 8; nt++) {
        const int cc = nt * 4 + t;
        if (r0 < n)
            hs2[(size_t)r0 * 32 + cc] =
                __floats2half2_rn(c[nt][0] * d0, c[nt][1] * d0);
        if (r1 < n)
            hs2[(size_t)r1 * 32 + cc] =
                __floats2half2_rn(c[nt][2] * d1, c[nt][3] * d1);
    }
}

// ---------------- launch -----------------------------------------------------
extern "C" void kernel_launch(void* const* d_in, const int* in_sizes, int n_in,
                              void* d_out, int out_size) {
    const float* x   = (const float*)d_in[0];
    const int*   ei  = (const int*)d_in[1];
    const float* W1  = (const float*)d_in[2];
    const float* b1  = (const float*)d_in[3];
    const float* g1  = (const float*)d_in[4];
    const float* be1 = (const float*)d_in[5];
    const float* W2  = (const float*)d_in[6];
    const float* b2  = (const float*)d_in[7];
    const float* g2  = (const float*)d_in[8];
    const float* be2 = (const float*)d_in[9];
    const float* W3  = (const float*)d_in[10];
    const float* b3  = (const float*)d_in[11];
    const float* g3  = (const float*)d_in[12];
    const float* be3 = (const float*)d_in[13];
    const float* Wh  = (const float*)d_in[14];
    const float* bh  = (const float*)d_in[15];
    float* out = (float*)d_out;

    const int n = in_sizes[0] / 128;
    const int e = in_sizes[1] / 2;
    const int* srcs = ei;
    const int* dsts = ei + e;

    const int SM128 = (64 * 132 + 128 * 68) * 4;   // gemm1 dynamic smem

    static __half* hsA = nullptr;
    static __half* hsB = nullptr;
    if (!hsA) {
        cudaGetSymbolAddress((void**)&hsA, g_hsA);
        cudaGetSymbolAddress((void**)&hsB, g_hsB);
        cudaFuncSetAttribute(gemm_tf32_kernel<128>,
                             cudaFuncAttributeMaxDynamicSharedMemorySize, SM128);
    }

    const int EB = (e + 255) / 256;
    const int SB = (n + SCAN_B - 1) / SCAN_B;  // scan blocks (<= 98)
    const int GB = (n + 63) / 64;              // 64 rows/block
    const int WB = (n + 7) / 8;                // head blocks (8 warps/block)

    // CSR build (deg is zeroed at module load and re-zeroed by scanA)
    count_deg_kernel<<<EB, 256>>>(dsts, e);
    scanA_kernel<<<SB, SCAN_B>>>(n);           // + fused dinv + deg re-zero
    scanC_kernel<<<SB, SCAN_B>>>(n, e);        // + folded scanB + cursor init
    place_kernel<<<EB, 256>>>(srcs, dsts, e);

    // Layer 1 GEMM (IN=128) -> hsA
    gemm_tf32_kernel<128><<<GB, 128, SM128>>>(x, W1, n);
    // Layer 1 gather + LN + GELU + Layer 2 GEMM -> hsB
    fused_gather_gemm_kernel<<<GB, 256>>>(hsA, b1, g1, be1, W2, hsB, n);
    // Layer 2 gather + LN + GELU + Layer 3 GEMM -> hsA
    fused_gather_gemm_kernel<<<GB, 256>>>(hsB, b2, g2, be2, W3, hsA, n);
    // Layer 3 gather + LN + GELU + head -> out
    gather_head_kernel<<<WB, 256>>>(hsA, b3, g3, be3, Wh, bh, out, n);
}

// round 12
// speedup vs baseline: 1.0199x; 1.0199x over previous
#include <cuda_runtime.h>
#include <cuda_fp16.h>
#include <cstdint>

// Problem constants (shapes are fixed by the dataset)
#define MAXN 100000
#define MAXE 1600000
#define HDIM 64
#define SCAN_B 1024

// ---------------- scratch (no allocations allowed -> __device__ globals) ----
__device__ int    g_deg[MAXN];                 // zero at load; re-zeroed by scanAC
__device__ float  g_dinv[MAXN];
__device__ int    g_rowstart[MAXN + 1];
__device__ int    g_cursor[MAXN];
__device__ int    g_esrc[MAXE];
__device__ int    g_blocksum[1024];
__device__ int    g_arrive;                    // grid-barrier counter (reset by count)
__device__ __half g_hsA[(size_t)MAXN * HDIM];  // fp16 hs, buffer A
__device__ __half g_hsB[(size_t)MAXN * HDIM];  // fp16 hs, buffer B

// ---------------- helpers ----------------------------------------------------
__device__ __forceinline__ unsigned long long pack2(float x, float y) {
    unsigned long long r;
    asm("mov.b64 %0, {%1,%2};" : "=l"(r) : "f"(x), "f"(y));
    return r;
}
__device__ __forceinline__ unsigned long long add2(unsigned long long a,
                                                   unsigned long long b) {
    unsigned long long d;
    asm("add.rn.f32x2 %0, %1, %2;" : "=l"(d) : "l"(a), "l"(b));
    return d;
}
__device__ __forceinline__ float2 unpack2(unsigned long long v) {
    float2 f;
    asm("mov.b64 {%0,%1}, %2;" : "=f"(f.x), "=f"(f.y) : "l"(v));
    return f;
}
__device__ __forceinline__ unsigned f2tf32(float x) {
    unsigned r;
    asm("cvt.rna.tf32.f32 %0, %1;" : "=r"(r) : "f"(x));
    return r;
}
__device__ __forceinline__ void mma_tf32(float& c0, float& c1, float& c2, float& c3,
                                         unsigned a0, unsigned a1, unsigned a2,
                                         unsigned a3, unsigned b0, unsigned b1) {
    asm("mma.sync.aligned.m16n8k8.row.col.f32.tf32.tf32.f32 "
        "{%0,%1,%2,%3}, {%4,%5,%6,%7}, {%8,%9}, {%0,%1,%2,%3};"
        : "+f"(c0), "+f"(c1), "+f"(c2), "+f"(c3)
        : "r"(a0), "r"(a1), "r"(a2), "r"(a3), "r"(b0), "r"(b1));
}
// add 4 fp16 values (one u64) into 2 packed-f32x2 accumulators
__device__ __forceinline__ void acc_h4(unsigned long long v,
                                       unsigned long long& a01,
                                       unsigned long long& a23) {
    const unsigned lo = (unsigned)v, hi = (unsigned)(v >> 32);
    const float2 f0 = __half22float2(*reinterpret_cast<const __half2*>(&lo));
    const float2 f1 = __half22float2(*reinterpret_cast<const __half2*>(&hi));
    a01 = add2(a01, pack2(f0.x, f0.y));
    a23 = add2(a23, pack2(f1.x, f1.y));
}

// ---------------- CSR build --------------------------------------------------
// 2 edges/thread; also resets the scan grid-barrier counter (stream-ordered
// before scanAC, so no replay hazard).
__global__ void count_deg_kernel(const int* __restrict__ dst, int e) {
    const int i = blockIdx.x * blockDim.x + threadIdx.x;
    if (i == 0) g_arrive = 0;
    const int j = i * 2;
    if (j + 1 < e) {
        const int2 d = ((const int2*)dst)[i];
        atomicAdd(&g_deg[d.x], 1);
        atomicAdd(&g_deg[d.y], 1);
    } else if (j < e) {
        atomicAdd(&g_deg[dst[j]], 1);
    }
}

// Merged scan: per-block exclusive scan of g_deg (+dinv, +deg re-zero), then
// an in-kernel grid barrier (all <=98 blocks co-resident on 148 SMs), then
// each block warp-reduces its prefix of blocksums and writes rowstart+cursor.
__global__ void __launch_bounds__(SCAN_B)
scanAC_kernel(int n, int e) {
    __shared__ int sh[SCAN_B];
    __shared__ int s_off;
    const int t = threadIdx.x;
    const int bid = blockIdx.x;
    const int i = bid * SCAN_B + t;
    const int v = (i < n) ? g_deg[i] : 0;
    if (i < n) {
        g_dinv[i] = rsqrtf((float)v + 1.0f);
        g_deg[i] = 0;                       // ready for next replay
    }
    sh[t] = v;
    __syncthreads();
    int acc = v;
#pragma unroll
    for (int off = 1; off < SCAN_B; off <<= 1) {
        int u = (t >= off) ? sh[t - off] : 0;
        __syncthreads();
        acc += u;
        sh[t] = acc;
        __syncthreads();
    }
    const int local_excl = acc - v;
    if (t == SCAN_B - 1) g_blocksum[bid] = acc;
    __threadfence();
    __syncthreads();                        // blocksum written before arrive
    if (t == 0) {
        atomicAdd(&g_arrive, 1);
        while (*(volatile int*)&g_arrive < gridDim.x) { }
    }
    __syncthreads();                        // all blocksums now visible
    __threadfence();

    if (t < 32) {
        int s = 0;
        for (int j = t; j < bid; j += 32) s += g_blocksum[j];  // <= 4 iters
#pragma unroll
        for (int o = 16; o > 0; o >>= 1)
            s += __shfl_xor_sync(0xffffffffu, s, o);
        if (t == 0) s_off = s;
    }
    __syncthreads();
    if (i < n) {
        const int r = local_excl + s_off;
        g_rowstart[i] = r;
        g_cursor[i]   = r;
    }
    if (i == 0) g_rowstart[n] = e;
}

// 2 edges/thread.
__global__ void place_kernel(const int* __restrict__ src,
                             const int* __restrict__ dst, int e) {
    const int i = blockIdx.x * blockDim.x + threadIdx.x;
    const int j = i * 2;
    if (j + 1 < e) {
        const int2 d = ((const int2*)dst)[i];
        const int2 s = ((const int2*)src)[i];
        const int p0 = atomicAdd(&g_cursor[d.x], 1);
        const int p1 = atomicAdd(&g_cursor[d.y], 1);
        g_esrc[p0] = s.x;
        g_esrc[p1] = s.y;
    } else if (j < e) {
        const int pos = atomicAdd(&g_cursor[dst[j]], 1);
        g_esrc[pos] = src[j];
    }
}

// ---------------- gather core (warp, one node) -> 4 post-GELU floats --------
// lane layout: h = lane>>4 (edge of pair), q = lane&15 (cols 4q..4q+3).
__device__ __forceinline__ void gather_node(const __half* __restrict__ hsin,
                                            int node, int lane, int h, int q,
                                            const float* __restrict__ b,
                                            const float* __restrict__ g,
                                            const float* __restrict__ be,
                                            float& u0, float& u1,
                                            float& u2, float& u3) {
    const int s0 = g_rowstart[node];
    const int s1 = g_rowstart[node + 1];
    const unsigned long long* hsp = (const unsigned long long*)hsin;  // 16/row

    unsigned long long aA01 = 0ull, aA23 = 0ull;
    unsigned long long aB01 = 0ull, aB23 = 0ull;

    for (int e = s0; e < s1; e += 32) {
        const int cnt = min(32, s1 - e);
        const int s = (lane < cnt) ? __ldg(&g_esrc[e + lane]) : 0;
        int i = 0;
        for (; i + 4 <= cnt; i += 4) {           // 2 pairs = 4 edges per iter
            const int sa = __shfl_sync(0xffffffffu, s, i + h);
            const int sb = __shfl_sync(0xffffffffu, s, i + 2 + h);
            const unsigned long long va = __ldg(&hsp[(size_t)sa * 16 + q]);
            const unsigned long long vb = __ldg(&hsp[(size_t)sb * 16 + q]);
            acc_h4(va, aA01, aA23);
            acc_h4(vb, aB01, aB23);
        }
        for (; i < cnt; i += 2) {                // pair tail
            const int idx = i + h;
            const int sa = __shfl_sync(0xffffffffu, s, idx & 31);
            if (idx < cnt)
                acc_h4(__ldg(&hsp[(size_t)sa * 16 + q]), aA01, aA23);
        }
    }

    if (h == 0)                                  // self-loop term, once
        acc_h4(__ldg(&hsp[(size_t)node * 16 + q]), aA01, aA23);

    aA01 = add2(aA01, aB01);
    aA23 = add2(aA23, aB23);
    const float2 p01 = unpack2(aA01);
    const float2 p23 = unpack2(aA23);
    float4 acc = make_float4(p01.x, p01.y, p23.x, p23.y);
    acc.x += __shfl_xor_sync(0xffffffffu, acc.x, 16);
    acc.y += __shfl_xor_sync(0xffffffffu, acc.y, 16);
    acc.z += __shfl_xor_sync(0xffffffffu, acc.z, 16);
    acc.w += __shfl_xor_sync(0xffffffffu, acc.w, 16);

    const float dv = g_dinv[node];
    const float4 b4 = __ldg(&((const float4*)b)[q]);
    float v0 = dv * acc.x + b4.x;
    float v1 = dv * acc.y + b4.y;
    float v2 = dv * acc.z + b4.z;
    float v3 = dv * acc.w + b4.w;

    // LayerNorm over 64 values
    float s  = v0 + v1 + v2 + v3;
    float sq = v0 * v0 + v1 * v1 + v2 * v2 + v3 * v3;
#pragma unroll
    for (int o = 8; o > 0; o >>= 1) {
        s  += __shfl_xor_sync(0xffffffffu, s, o);
        sq += __shfl_xor_sync(0xffffffffu, sq, o);
    }
    const float mu   = s * (1.0f / 64.0f);
    const float var  = sq * (1.0f / 64.0f) - mu * mu;
    const float rstd = rsqrtf(var + 1e-5f);

    const float4 g4  = __ldg(&((const float4*)g)[q]);
    const float4 be4 = __ldg(&((const float4*)be)[q]);
    u0 = (v0 - mu) * rstd * g4.x + be4.x;
    u1 = (v1 - mu) * rstd * g4.y + be4.y;
    u2 = (v2 - mu) * rstd * g4.z + be4.z;
    u3 = (v3 - mu) * rstd * g4.w + be4.w;

    const float k = 0.70710678118654752f;
    u0 = 0.5f * u0 * (1.0f + erff(u0 * k));
    u1 = 0.5f * u1 * (1.0f + erff(u1 * k));
    u2 = 0.5f * u2 * (1.0f + erff(u2 * k));
    u3 = 0.5f * u3 * (1.0f + erff(u3 * k));
}

// ---------------- fused: gather+LN+GELU -> smem tf32 -> MMA W -> fp16 hsout --
// Block = 256 thr / 8 warps / 64 nodes (8 per warp). Double-buffered hs.
__global__ void __launch_bounds__(256)
fused_gather_gemm_kernel(const __half* __restrict__ hsin,
                         const float* __restrict__ b, const float* __restrict__ g,
                         const float* __restrict__ be, const float* __restrict__ Wn,
                         __half* __restrict__ hsout, int n) {
    constexpr int S = HDIM + 4;                  // padded stride (tf32 words)
    __shared__ unsigned Ys[64 * S];              // post-GELU rows (tf32)
    __shared__ unsigned Ws[HDIM * S];            // next-layer W (tf32)

    const int tid  = threadIdx.x;
    const int rb   = blockIdx.x * 64;
    const int warp = tid >> 5;
    const int lane = tid & 31;

    // Stage W (tf32)
    const float4* W4 = (const float4*)Wn;
    for (int idx = tid; idx < HDIM * (HDIM / 4); idx += 256) {
        const int k  = idx / (HDIM / 4);
        const int c4 = idx % (HDIM / 4);
        const float4 v = __ldg(&W4[(size_t)k * (HDIM / 4) + c4]);
        unsigned* d = Ws + k * S + c4 * 4;
        d[0] = f2tf32(v.x); d[1] = f2tf32(v.y);
        d[2] = f2tf32(v.z); d[3] = f2tf32(v.w);
    }

    // Gather phase: warp w handles nodes rb + w*8 .. rb + w*8 + 7
    {
        const int h = lane >> 4;
        const int q = lane & 15;
#pragma unroll 1
        for (int j = 0; j < 8; j++) {
            const int lrow = warp * 8 + j;
            const int node = rb + lrow;
            if (node < n) {
                float u0, u1, u2, u3;
                gather_node(hsin, node, lane, h, q, b, g, be, u0, u1, u2, u3);
                if (h == 0) {
                    unsigned* d = Ys + lrow * S + q * 4;
                    d[0] = f2tf32(u0); d[1] = f2tf32(u1);
                    d[2] = f2tf32(u2); d[3] = f2tf32(u3);
                }
            } else if (h == 0) {
                unsigned* d = Ys + lrow * S + q * 4;
                d[0] = 0u; d[1] = 0u; d[2] = 0u; d[3] = 0u;
            }
        }
    }
    __syncthreads();

    // MMA phase: warp w -> row-group rg = w>>1 (16 rows), col-half ch = w&1
    {
        const int rg = warp >> 1;
        const int ch = warp & 1;
        const int gg = lane >> 2;
        const int t  = lane & 3;

        float c[4][4];
#pragma unroll
        for (int i = 0; i < 4; i++)
#pragma unroll
            for (int j = 0; j < 4; j++) c[i][j] = 0.f;

        const unsigned* Yw = Ys + (rg * 16) * S;
#pragma unroll
        for (int ks = 0; ks < HDIM / 8; ks++) {
            const int kb = ks * 8;
            const unsigned a0 = Yw[gg * S + kb + t];
            const unsigned a1 = Yw[(gg + 8) * S + kb + t];
            const unsigned a2 = Yw[gg * S + kb + t + 4];
            const unsigned a3 = Yw[(gg + 8) * S + kb + t + 4];
#pragma unroll
            for (int nti = 0; nti < 4; nti++) {
                const int nt = ch * 4 + nti;
                const unsigned b0 = Ws[(kb + t) * S + nt * 8 + gg];
                const unsigned b1 = Ws[(kb + t + 4) * S + nt * 8 + gg];
                mma_tf32(c[nti][0], c[nti][1], c[nti][2], c[nti][3],
                         a0, a1, a2, a3, b0, b1);
            }
        }

        const int r0 = rb + rg * 16 + gg;
        const int r1 = r0 + 8;
        const float d0 = __ldg(&g_dinv[min(r0, n - 1)]);
        const float d1 = __ldg(&g_dinv[min(r1, n - 1)]);
        __half2* hs2 = (__half2*)hsout;          // 32 half2 per row
#pragma unroll
        for (int nti = 0; nti < 4; nti++) {
            const int nt = ch * 4 + nti;
            const int cc = nt * 4 + t;
            if (r0 < n)
                hs2[(size_t)r0 * 32 + cc] =
                    __floats2half2_rn(c[nti][0] * d0, c[nti][1] * d0);
            if (r1 < n)
                hs2[(size_t)r1 * 32 + cc] =
                    __floats2half2_rn(c[nti][2] * d1, c[nti][3] * d1);
        }
    }
}

// ---------------- final gather + head: out[node] = gelu(ln(agg)) @ Wh + bh ---
__global__ void __launch_bounds__(256)
gather_head_kernel(const __half* __restrict__ hsin,
                   const float* __restrict__ b, const float* __restrict__ g,
                   const float* __restrict__ be, const float* __restrict__ Wh,
                   const float* __restrict__ bh, float* __restrict__ out, int n) {
    const int warp = (blockIdx.x * blockDim.x + threadIdx.x) >> 5;
    const int lane = threadIdx.x & 31;
    if (warp >= n) return;
    const int h = lane >> 4;
    const int q = lane & 15;

    float u0, u1, u2, u3;
    gather_node(hsin, warp, lane, h, q, b, g, be, u0, u1, u2, u3);

    const float4 w4 = __ldg(&((const float4*)Wh)[q]);
    float p = u0 * w4.x + u1 * w4.y + u2 * w4.z + u3 * w4.w;
#pragma unroll
    for (int o = 8; o > 0; o >>= 1) p += __shfl_xor_sync(0xffffffffu, p, o);
    if (lane == 0) out[warp] = p + __ldg(&bh[0]);
}

// ---------------- layer-1 GEMM (tensor cores): hsA = fp16((X @ W1) * dinv) --
template <int KDIM>
__global__ void __launch_bounds__(128)
gemm_tf32_kernel(const float* __restrict__ X, const float* __restrict__ W, int n) {
    constexpr int SX = KDIM + 4;
    constexpr int SW = HDIM + 4;
    extern __shared__ unsigned sm[];
    unsigned* Xs = sm;
    unsigned* Ws = sm + 64 * SX;

    const int tid = threadIdx.x;
    const int rb  = blockIdx.x * 64;

    const float4* X4 = (const float4*)X;
    for (int idx = tid; idx < 64 * (KDIM / 4); idx += 128) {
        const int row = idx / (KDIM / 4);
        const int c4  = idx % (KDIM / 4);
        const int gr  = min(rb + row, n - 1);
        const float4 v = X4[(size_t)gr * (KDIM / 4) + c4];
        unsigned* d = Xs + row * SX + c4 * 4;
        d[0] = f2tf32(v.x); d[1] = f2tf32(v.y);
        d[2] = f2tf32(v.z); d[3] = f2tf32(v.w);
    }
    const float4* W4 = (const float4*)W;
    for (int idx = tid; idx < KDIM * (HDIM / 4); idx += 128) {
        const int k  = idx / (HDIM / 4);
        const int c4 = idx % (HDIM / 4);
        const float4 v = W4[(size_t)k * (HDIM / 4) + c4];
        unsigned* d = Ws + k * SW + c4 * 4;
        d[0] = f2tf32(v.x); d[1] = f2tf32(v.y);
        d[2] = f2tf32(v.z); d[3] = f2tf32(v.w);
    }
    __syncthreads();

    const int warp = tid >> 5;
    const int lane = tid & 31;
    const int g = lane >> 2;
    const int t = lane & 3;
    const unsigned* Xw = Xs + (warp * 16) * SX;

    float c[8][4];
#pragma unroll
    for (int nt = 0; nt < 8; nt++)
#pragma unroll
        for (int j = 0; j < 4; j++) c[nt][j] = 0.f;

#pragma unroll
    for (int ks = 0; ks < KDIM / 8; ks++) {
        const int kb = ks * 8;
        const unsigned a0 = Xw[g * SX + kb + t];
        const unsigned a1 = Xw[(g + 8) * SX + kb + t];
        const unsigned a2 = Xw[g * SX + kb + t + 4];
        const unsigned a3 = Xw[(g + 8) * SX + kb + t + 4];
#pragma unroll
        for (int nt = 0; nt < 8; nt++) {
            const unsigned b0 = Ws[(kb + t) * SW + nt * 8 + g];
            const unsigned b1 = Ws[(kb + t + 4) * SW + nt * 8 + g];
            mma_tf32(c[nt][0], c[nt][1], c[nt][2], c[nt][3],
                     a0, a1, a2, a3, b0, b1);
        }
    }

    const int r0 = rb + warp * 16 + g;
    const int r1 = r0 + 8;
    const float d0 = __ldg(&g_dinv[min(r0, n - 1)]);
    const float d1 = __ldg(&g_dinv[min(r1, n - 1)]);
    __half2* hs2 = (__half2*)g_hsA;
#pragma unroll
    for (int nt = 0; nt < 8; nt++) {
        const int cc = nt * 4 + t;
        if (r0 < n)
            hs2[(size_t)r0 * 32 + cc] =
                __floats2half2_rn(c[nt][0] * d0, c[nt][1] * d0);
        if (r1 < n)
            hs2[(size_t)r1 * 32 + cc] =
                __floats2half2_rn(c[nt][2] * d1, c[nt][3] * d1);
    }
}

// ---------------- launch -----------------------------------------------------
extern "C" void kernel_launch(void* const* d_in, const int* in_sizes, int n_in,
                              void* d_out, int out_size) {
    const float* x   = (const float*)d_in[0];
    const int*   ei  = (const int*)d_in[1];
    const float* W1  = (const float*)d_in[2];
    const float* b1  = (const float*)d_in[3];
    const float* g1  = (const float*)d_in[4];
    const float* be1 = (const float*)d_in[5];
    const float* W2  = (const float*)d_in[6];
    const float* b2  = (const float*)d_in[7];
    const float* g2  = (const float*)d_in[8];
    const float* be2 = (const float*)d_in[9];
    const float* W3  = (const float*)d_in[10];
    const float* b3  = (const float*)d_in[11];
    const float* g3  = (const float*)d_in[12];
    const float* be3 = (const float*)d_in[13];
    const float* Wh  = (const float*)d_in[14];
    const float* bh  = (const float*)d_in[15];
    float* out = (float*)d_out;

    const int n = in_sizes[0] / 128;
    const int e = in_sizes[1] / 2;
    const int* srcs = ei;
    const int* dsts = ei + e;

    const int SM128 = (64 * 132 + 128 * 68) * 4;   // gemm1 dynamic smem

    static __half* hsA = nullptr;
    static __half* hsB = nullptr;
    if (!hsA) {
        cudaGetSymbolAddress((void**)&hsA, g_hsA);
        cudaGetSymbolAddress((void**)&hsB, g_hsB);
        cudaFuncSetAttribute(gemm_tf32_kernel<128>,
                             cudaFuncAttributeMaxDynamicSharedMemorySize, SM128);
    }

    const int E2B = (e / 2 + 255) / 256;       // 2 edges/thread blocks
    const int SB = (n + SCAN_B - 1) / SCAN_B;  // scan blocks (<= 98, co-resident)
    const int GB = (n + 63) / 64;              // 64 rows/block
    const int WB = (n + 7) / 8;                // head blocks (8 warps/block)

    // CSR build: count (also resets grid-barrier ctr) -> merged scan -> place
    count_deg_kernel<<<E2B, 256>>>(dsts, e);
    scanAC_kernel<<<SB, SCAN_B>>>(n, e);       // scan + dinv + cursor, 1 kernel
    place_kernel<<<E2B, 256>>>(srcs, dsts, e);

    // Layer 1 GEMM (IN=128) -> hsA
    gemm_tf32_kernel<128><<<GB, 128, SM128>>>(x, W1, n);
    // Layer 1 gather + LN + GELU + Layer 2 GEMM -> hsB
    fused_gather_gemm_kernel<<<GB, 256>>>(hsA, b1, g1, be1, W2, hsB, n);
    // Layer 2 gather + LN + GELU + Layer 3 GEMM -> hsA
    fused_gather_gemm_kernel<<<GB, 256>>>(hsB, b2, g2, be2, W3, hsA, n);
    // Layer 3 gather + LN + GELU + head -> out
    gather_head_kernel<<<WB, 256>>>(hsA, b3, g3, be3, Wh, bh, out, n);
}

// round 13
// speedup vs baseline: 1.0515x; 1.0310x over previous
#include <cuda_runtime.h>
#include <cuda_fp16.h>
#include <cstdint>

// Problem constants (shapes are fixed by the dataset)
#define MAXN 100000
#define MAXE 1600000
#define HDIM 64
#define SCAN_B 1024

// ---------------- scratch (no allocations allowed -> __device__ globals) ----
__device__ int    g_deg[MAXN];                 // zero at load; re-zeroed by scanAC
__device__ float  g_dinv[MAXN];
__device__ int    g_rowstart[MAXN + 1];
__device__ int    g_cursor[MAXN];
__device__ int    g_esrc[MAXE];
__device__ int    g_blocksum[1024];
__device__ int    g_arrive;                    // grid-barrier counter (reset by count)
__device__ __half g_hsA[(size_t)MAXN * HDIM];  // fp16 hs, buffer A
__device__ __half g_hsB[(size_t)MAXN * HDIM];  // fp16 hs, buffer B

// ---------------- helpers ----------------------------------------------------
__device__ __forceinline__ unsigned long long pack2(float x, float y) {
    unsigned long long r;
    asm("mov.b64 %0, {%1,%2};" : "=l"(r) : "f"(x), "f"(y));
    return r;
}
__device__ __forceinline__ unsigned long long add2(unsigned long long a,
                                                   unsigned long long b) {
    unsigned long long d;
    asm("add.rn.f32x2 %0, %1, %2;" : "=l"(d) : "l"(a), "l"(b));
    return d;
}
__device__ __forceinline__ float2 unpack2(unsigned long long v) {
    float2 f;
    asm("mov.b64 {%0,%1}, %2;" : "=f"(f.x), "=f"(f.y) : "l"(v));
    return f;
}
__device__ __forceinline__ unsigned f2tf32(float x) {
    unsigned r;
    asm("cvt.rna.tf32.f32 %0, %1;" : "=r"(r) : "f"(x));
    return r;
}
__device__ __forceinline__ void mma_tf32(float& c0, float& c1, float& c2, float& c3,
                                         unsigned a0, unsigned a1, unsigned a2,
                                         unsigned a3, unsigned b0, unsigned b1) {
    asm("mma.sync.aligned.m16n8k8.row.col.f32.tf32.tf32.f32 "
        "{%0,%1,%2,%3}, {%4,%5,%6,%7}, {%8,%9}, {%0,%1,%2,%3};"
        : "+f"(c0), "+f"(c1), "+f"(c2), "+f"(c3)
        : "r"(a0), "r"(a1), "r"(a2), "r"(a3), "r"(b0), "r"(b1));
}
// add 4 fp16 values (one u64) into 2 packed-f32x2 accumulators
__device__ __forceinline__ void acc_h4(unsigned long long v,
                                       unsigned long long& a01,
                                       unsigned long long& a23) {
    const unsigned lo = (unsigned)v, hi = (unsigned)(v >> 32);
    const float2 f0 = __half22float2(*reinterpret_cast<const __half2*>(&lo));
    const float2 f1 = __half22float2(*reinterpret_cast<const __half2*>(&hi));
    a01 = add2(a01, pack2(f0.x, f0.y));
    a23 = add2(a23, pack2(f1.x, f1.y));
}

// ---------------- CSR build --------------------------------------------------
// 2 edges/thread; also resets the scan grid-barrier counter (stream-ordered
// before scanAC, so no replay hazard).
__global__ void count_deg_kernel(const int* __restrict__ dst, int e) {
    const int i = blockIdx.x * blockDim.x + threadIdx.x;
    if (i == 0) g_arrive = 0;
    const int j = i * 2;
    if (j + 1 < e) {
        const int2 d = ((const int2*)dst)[i];
        atomicAdd(&g_deg[d.x], 1);
        atomicAdd(&g_deg[d.y], 1);
    } else if (j < e) {
        atomicAdd(&g_deg[dst[j]], 1);
    }
}

// Merged scan: per-block exclusive scan of g_deg (+dinv, +deg re-zero), then
// an in-kernel grid barrier (all <=98 blocks co-resident on 148 SMs), then
// each block warp-reduces its prefix of blocksums and writes rowstart+cursor.
__global__ void __launch_bounds__(SCAN_B)
scanAC_kernel(int n, int e) {
    __shared__ int sh[SCAN_B];
    __shared__ int s_off;
    const int t = threadIdx.x;
    const int bid = blockIdx.x;
    const int i = bid * SCAN_B + t;
    const int v = (i < n) ? g_deg[i] : 0;
    if (i < n) {
        g_dinv[i] = rsqrtf((float)v + 1.0f);
        g_deg[i] = 0;                       // ready for next replay
    }
    sh[t] = v;
    __syncthreads();
    int acc = v;
#pragma unroll
    for (int off = 1; off < SCAN_B; off <<= 1) {
        int u = (t >= off) ? sh[t - off] : 0;
        __syncthreads();
        acc += u;
        sh[t] = acc;
        __syncthreads();
    }
    const int local_excl = acc - v;
    if (t == SCAN_B - 1) g_blocksum[bid] = acc;
    __threadfence();
    __syncthreads();                        // blocksum written before arrive
    if (t == 0) {
        atomicAdd(&g_arrive, 1);
        while (*(volatile int*)&g_arrive < gridDim.x) { }
    }
    __syncthreads();                        // all blocksums now visible
    __threadfence();

    if (t < 32) {
        int s = 0;
        for (int j = t; j < bid; j += 32) s += g_blocksum[j];  // <= 4 iters
#pragma unroll
        for (int o = 16; o > 0; o >>= 1)
            s += __shfl_xor_sync(0xffffffffu, s, o);
        if (t == 0) s_off = s;
    }
    __syncthreads();
    if (i < n) {
        const int r = local_excl + s_off;
        g_rowstart[i] = r;
        g_cursor[i]   = r;
    }
    if (i == 0) g_rowstart[n] = e;
}

// 2 edges/thread.
__global__ void place_kernel(const int* __restrict__ src,
                             const int* __restrict__ dst, int e) {
    const int i = blockIdx.x * blockDim.x + threadIdx.x;
    const int j = i * 2;
    if (j + 1 < e) {
        const int2 d = ((const int2*)dst)[i];
        const int2 s = ((const int2*)src)[i];
        const int p0 = atomicAdd(&g_cursor[d.x], 1);
        const int p1 = atomicAdd(&g_cursor[d.y], 1);
        g_esrc[p0] = s.x;
        g_esrc[p1] = s.y;
    } else if (j < e) {
        const int pos = atomicAdd(&g_cursor[dst[j]], 1);
        g_esrc[pos] = src[j];
    }
}

// ---------------- gather core (warp, one node) -> 4 post-GELU floats --------
// lane layout: h = lane>>4 (edge of pair), q = lane&15 (cols 4q..4q+3).
__device__ __forceinline__ void gather_node(const __half* __restrict__ hsin,
                                            int node, int lane, int h, int q,
                                            const float* __restrict__ b,
                                            const float* __restrict__ g,
                                            const float* __restrict__ be,
                                            float& u0, float& u1,
                                            float& u2, float& u3) {
    const int s0 = g_rowstart[node];
    const int s1 = g_rowstart[node + 1];
    const unsigned long long* hsp = (const unsigned long long*)hsin;  // 16/row

    unsigned long long aA01 = 0ull, aA23 = 0ull;
    unsigned long long aB01 = 0ull, aB23 = 0ull;

    for (int e = s0; e < s1; e += 32) {
        const int cnt = min(32, s1 - e);
        const int s = (lane < cnt) ? __ldg(&g_esrc[e + lane]) : 0;
        int i = 0;
        for (; i + 4 <= cnt; i += 4) {           // 2 pairs = 4 edges per iter
            const int sa = __shfl_sync(0xffffffffu, s, i + h);
            const int sb = __shfl_sync(0xffffffffu, s, i + 2 + h);
            const unsigned long long va = __ldg(&hsp[(size_t)sa * 16 + q]);
            const unsigned long long vb = __ldg(&hsp[(size_t)sb * 16 + q]);
            acc_h4(va, aA01, aA23);
            acc_h4(vb, aB01, aB23);
        }
        for (; i < cnt; i += 2) {                // pair tail
            const int idx = i + h;
            const int sa = __shfl_sync(0xffffffffu, s, idx & 31);
            if (idx < cnt)
                acc_h4(__ldg(&hsp[(size_t)sa * 16 + q]), aA01, aA23);
        }
    }

    if (h == 0)                                  // self-loop term, once
        acc_h4(__ldg(&hsp[(size_t)node * 16 + q]), aA01, aA23);

    aA01 = add2(aA01, aB01);
    aA23 = add2(aA23, aB23);
    const float2 p01 = unpack2(aA01);
    const float2 p23 = unpack2(aA23);
    float4 acc = make_float4(p01.x, p01.y, p23.x, p23.y);
    acc.x += __shfl_xor_sync(0xffffffffu, acc.x, 16);
    acc.y += __shfl_xor_sync(0xffffffffu, acc.y, 16);
    acc.z += __shfl_xor_sync(0xffffffffu, acc.z, 16);
    acc.w += __shfl_xor_sync(0xffffffffu, acc.w, 16);

    const float dv = g_dinv[node];
    const float4 b4 = __ldg(&((const float4*)b)[q]);
    float v0 = dv * acc.x + b4.x;
    float v1 = dv * acc.y + b4.y;
    float v2 = dv * acc.z + b4.z;
    float v3 = dv * acc.w + b4.w;

    // LayerNorm over 64 values
    float s  = v0 + v1 + v2 + v3;
    float sq = v0 * v0 + v1 * v1 + v2 * v2 + v3 * v3;
#pragma unroll
    for (int o = 8; o > 0; o >>= 1) {
        s  += __shfl_xor_sync(0xffffffffu, s, o);
        sq += __shfl_xor_sync(0xffffffffu, sq, o);
    }
    const float mu   = s * (1.0f / 64.0f);
    const float var  = sq * (1.0f / 64.0f) - mu * mu;
    const float rstd = rsqrtf(var + 1e-5f);

    const float4 g4  = __ldg(&((const float4*)g)[q]);
    const float4 be4 = __ldg(&((const float4*)be)[q]);
    u0 = (v0 - mu) * rstd * g4.x + be4.x;
    u1 = (v1 - mu) * rstd * g4.y + be4.y;
    u2 = (v2 - mu) * rstd * g4.z + be4.z;
    u3 = (v3 - mu) * rstd * g4.w + be4.w;

    const float k = 0.70710678118654752f;
    u0 = 0.5f * u0 * (1.0f + erff(u0 * k));
    u1 = 0.5f * u1 * (1.0f + erff(u1 * k));
    u2 = 0.5f * u2 * (1.0f + erff(u2 * k));
    u3 = 0.5f * u3 * (1.0f + erff(u3 * k));
}

// ---------------- fused: gather+LN+GELU -> smem tf32 -> MMA W -> fp16 hsout --
// Block = 256 thr / 8 warps / 64 nodes (8 per warp). Double-buffered hs.
__global__ void __launch_bounds__(256)
fused_gather_gemm_kernel(const __half* __restrict__ hsin,
                         const float* __restrict__ b, const float* __restrict__ g,
                         const float* __restrict__ be, const float* __restrict__ Wn,
                         __half* __restrict__ hsout, int n) {
    constexpr int S = HDIM + 4;                  // padded stride (tf32 words)
    __shared__ unsigned Ys[64 * S];              // post-GELU rows (tf32)
    __shared__ unsigned Ws[HDIM * S];            // next-layer W (tf32)

    const int tid  = threadIdx.x;
    const int rb   = blockIdx.x * 64;
    const int warp = tid >> 5;
    const int lane = tid & 31;

    // Stage W (tf32)
    const float4* W4 = (const float4*)Wn;
    for (int idx = tid; idx < HDIM * (HDIM / 4); idx += 256) {
        const int k  = idx / (HDIM / 4);
        const int c4 = idx % (HDIM / 4);
        const float4 v = __ldg(&W4[(size_t)k * (HDIM / 4) + c4]);
        unsigned* d = Ws + k * S + c4 * 4;
        d[0] = f2tf32(v.x); d[1] = f2tf32(v.y);
        d[2] = f2tf32(v.z); d[3] = f2tf32(v.w);
    }

    // Gather phase: warp w handles nodes rb + w*8 .. rb + w*8 + 7
    {
        const int h = lane >> 4;
        const int q = lane & 15;
#pragma unroll 1
        for (int j = 0; j < 8; j++) {
            const int lrow = warp * 8 + j;
            const int node = rb + lrow;
            if (node < n) {
                float u0, u1, u2, u3;
                gather_node(hsin, node, lane, h, q, b, g, be, u0, u1, u2, u3);
                if (h == 0) {
                    unsigned* d = Ys + lrow * S + q * 4;
                    d[0] = f2tf32(u0); d[1] = f2tf32(u1);
                    d[2] = f2tf32(u2); d[3] = f2tf32(u3);
                }
            } else if (h == 0) {
                unsigned* d = Ys + lrow * S + q * 4;
                d[0] = 0u; d[1] = 0u; d[2] = 0u; d[3] = 0u;
            }
        }
    }
    __syncthreads();

    // MMA phase: warp w -> row-group rg = w>>1 (16 rows), col-half ch = w&1
    {
        const int rg = warp >> 1;
        const int ch = warp & 1;
        const int gg = lane >> 2;
        const int t  = lane & 3;

        float c[4][4];
#pragma unroll
        for (int i = 0; i < 4; i++)
#pragma unroll
            for (int j = 0; j < 4; j++) c[i][j] = 0.f;

        const unsigned* Yw = Ys + (rg * 16) * S;
#pragma unroll
        for (int ks = 0; ks < HDIM / 8; ks++) {
            const int kb = ks * 8;
            const unsigned a0 = Yw[gg * S + kb + t];
            const unsigned a1 = Yw[(gg + 8) * S + kb + t];
            const unsigned a2 = Yw[gg * S + kb + t + 4];
            const unsigned a3 = Yw[(gg + 8) * S + kb + t + 4];
#pragma unroll
            for (int nti = 0; nti < 4; nti++) {
                const int nt = ch * 4 + nti;
                const unsigned b0 = Ws[(kb + t) * S + nt * 8 + gg];
                const unsigned b1 = Ws[(kb + t + 4) * S + nt * 8 + gg];
                mma_tf32(c[nti][0], c[nti][1], c[nti][2], c[nti][3],
                         a0, a1, a2, a3, b0, b1);
            }
        }

        const int r0 = rb + rg * 16 + gg;
        const int r1 = r0 + 8;
        const float d0 = __ldg(&g_dinv[min(r0, n - 1)]);
        const float d1 = __ldg(&g_dinv[min(r1, n - 1)]);
        __half2* hs2 = (__half2*)hsout;          // 32 half2 per row
#pragma unroll
        for (int nti = 0; nti < 4; nti++) {
            const int nt = ch * 4 + nti;
            const int cc = nt * 4 + t;
            if (r0 < n)
                hs2[(size_t)r0 * 32 + cc] =
                    __floats2half2_rn(c[nti][0] * d0, c[nti][1] * d0);
            if (r1 < n)
                hs2[(size_t)r1 * 32 + cc] =
                    __floats2half2_rn(c[nti][2] * d1, c[nti][3] * d1);
        }
    }
}

// ---------------- final gather + head: out[node] = gelu(ln(agg)) @ Wh + bh ---
__global__ void __launch_bounds__(256)
gather_head_kernel(const __half* __restrict__ hsin,
                   const float* __restrict__ b, const float* __restrict__ g,
                   const float* __restrict__ be, const float* __restrict__ Wh,
                   const float* __restrict__ bh, float* __restrict__ out, int n) {
    const int warp = (blockIdx.x * blockDim.x + threadIdx.x) >> 5;
    const int lane = threadIdx.x & 31;
    if (warp >= n) return;
    const int h = lane >> 4;
    const int q = lane & 15;

    float u0, u1, u2, u3;
    gather_node(hsin, warp, lane, h, q, b, g, be, u0, u1, u2, u3);

    const float4 w4 = __ldg(&((const float4*)Wh)[q]);
    float p = u0 * w4.x + u1 * w4.y + u2 * w4.z + u3 * w4.w;
#pragma unroll
    for (int o = 8; o > 0; o >>= 1) p += __shfl_xor_sync(0xffffffffu, p, o);
    if (lane == 0) out[warp] = p + __ldg(&bh[0]);
}

// ---------------- layer-1 GEMM (tensor cores): hsA = fp16((X @ W1) * dinv) --
// 256 thr / 8 warps / 128 rows per block: 2x warps/SM vs the 128-thr version
// at the same blocks/SM (smem ~100KB -> 2 blocks), and W staged half as often.
template <int KDIM>
__global__ void __launch_bounds__(256)
gemm_tf32_kernel(const float* __restrict__ X, const float* __restrict__ W, int n) {
    constexpr int SX = KDIM + 4;
    constexpr int SW = HDIM + 4;
    extern __shared__ unsigned sm[];
    unsigned* Xs = sm;                 // 128 rows x SX
    unsigned* Ws = sm + 128 * SX;      // KDIM rows x SW

    const int tid = threadIdx.x;
    const int rb  = blockIdx.x * 128;

    const float4* X4 = (const float4*)X;
    for (int idx = tid; idx < 128 * (KDIM / 4); idx += 256) {
        const int row = idx / (KDIM / 4);
        const int c4  = idx % (KDIM / 4);
        const int gr  = min(rb + row, n - 1);
        const float4 v = X4[(size_t)gr * (KDIM / 4) + c4];
        unsigned* d = Xs + row * SX + c4 * 4;
        d[0] = f2tf32(v.x); d[1] = f2tf32(v.y);
        d[2] = f2tf32(v.z); d[3] = f2tf32(v.w);
    }
    const float4* W4 = (const float4*)W;
    for (int idx = tid; idx < KDIM * (HDIM / 4); idx += 256) {
        const int k  = idx / (HDIM / 4);
        const int c4 = idx % (HDIM / 4);
        const float4 v = W4[(size_t)k * (HDIM / 4) + c4];
        unsigned* d = Ws + k * SW + c4 * 4;
        d[0] = f2tf32(v.x); d[1] = f2tf32(v.y);
        d[2] = f2tf32(v.z); d[3] = f2tf32(v.w);
    }
    __syncthreads();

    const int warp = tid >> 5;         // 8 warps x 16 rows = 128 rows
    const int lane = tid & 31;
    const int g = lane >> 2;
    const int t = lane & 3;
    const unsigned* Xw = Xs + (warp * 16) * SX;

    float c[8][4];
#pragma unroll
    for (int nt = 0; nt < 8; nt++)
#pragma unroll
        for (int j = 0; j < 4; j++) c[nt][j] = 0.f;

#pragma unroll
    for (int ks = 0; ks < KDIM / 8; ks++) {
        const int kb = ks * 8;
        const unsigned a0 = Xw[g * SX + kb + t];
        const unsigned a1 = Xw[(g + 8) * SX + kb + t];
        const unsigned a2 = Xw[g * SX + kb + t + 4];
        const unsigned a3 = Xw[(g + 8) * SX + kb + t + 4];
#pragma unroll
        for (int nt = 0; nt < 8; nt++) {
            const unsigned b0 = Ws[(kb + t) * SW + nt * 8 + g];
            const unsigned b1 = Ws[(kb + t + 4) * SW + nt * 8 + g];
            mma_tf32(c[nt][0], c[nt][1], c[nt][2], c[nt][3],
                     a0, a1, a2, a3, b0, b1);
        }
    }

    const int r0 = rb + warp * 16 + g;
    const int r1 = r0 + 8;
    const float d0 = __ldg(&g_dinv[min(r0, n - 1)]);
    const float d1 = __ldg(&g_dinv[min(r1, n - 1)]);
    __half2* hs2 = (__half2*)g_hsA;
#pragma unroll
    for (int nt = 0; nt < 8; nt++) {
        const int cc = nt * 4 + t;
        if (r0 < n)
            hs2[(size_t)r0 * 32 + cc] =
                __floats2half2_rn(c[nt][0] * d0, c[nt][1] * d0);
        if (r1 < n)
            hs2[(size_t)r1 * 32 + cc] =
                __floats2half2_rn(c[nt][2] * d1, c[nt][3] * d1);
    }
}

// ---------------- launch -----------------------------------------------------
extern "C" void kernel_launch(void* const* d_in, const int* in_sizes, int n_in,
                              void* d_out, int out_size) {
    const float* x   = (const float*)d_in[0];
    const int*   ei  = (const int*)d_in[1];
    const float* W1  = (const float*)d_in[2];
    const float* b1  = (const float*)d_in[3];
    const float* g1  = (const float*)d_in[4];
    const float* be1 = (const float*)d_in[5];
    const float* W2  = (const float*)d_in[6];
    const float* b2  = (const float*)d_in[7];
    const float* g2  = (const float*)d_in[8];
    const float* be2 = (const float*)d_in[9];
    const float* W3  = (const float*)d_in[10];
    const float* b3  = (const float*)d_in[11];
    const float* g3  = (const float*)d_in[12];
    const float* be3 = (const float*)d_in[13];
    const float* Wh  = (const float*)d_in[14];
    const float* bh  = (const float*)d_in[15];
    float* out = (float*)d_out;

    const int n = in_sizes[0] / 128;
    const int e = in_sizes[1] / 2;
    const int* srcs = ei;
    const int* dsts = ei + e;

    const int SM128 = (128 * 132 + 128 * 68) * 4;   // 102400 B dynamic smem

    static __half* hsA = nullptr;
    static __half* hsB = nullptr;
    if (!hsA) {
        cudaGetSymbolAddress((void**)&hsA, g_hsA);
        cudaGetSymbolAddress((void**)&hsB, g_hsB);
        cudaFuncSetAttribute(gemm_tf32_kernel<128>,
                             cudaFuncAttributeMaxDynamicSharedMemorySize, SM128);
    }

    const int E2B = (e / 2 + 255) / 256;       // 2 edges/thread blocks
    const int SB = (n + SCAN_B - 1) / SCAN_B;  // scan blocks (<= 98, co-resident)
    const int GB1 = (n + 127) / 128;           // gemm1 blocks (128 rows/block)
    const int GB = (n + 63) / 64;              // fused blocks (64 rows/block)
    const int WB = (n + 7) / 8;                // head blocks (8 warps/block)

    // CSR build: count (also resets grid-barrier ctr) -> merged scan -> place
    count_deg_kernel<<<E2B, 256>>>(dsts, e);
    scanAC_kernel<<<SB, SCAN_B>>>(n, e);       // scan + dinv + cursor, 1 kernel
    place_kernel<<<E2B, 256>>>(srcs, dsts, e);

    // Layer 1 GEMM (IN=128) -> hsA
    gemm_tf32_kernel<128><<<GB1, 256, SM128>>>(x, W1, n);
    // Layer 1 gather + LN + GELU + Layer 2 GEMM -> hsB
    fused_gather_gemm_kernel<<<GB, 256>>>(hsA, b1, g1, be1, W2, hsB, n);
    // Layer 2 gather + LN + GELU + Layer 3 GEMM -> hsA
    fused_gather_gemm_kernel<<<GB, 256>>>(hsB, b2, g2, be2, W3, hsA, n);
    // Layer 3 gather + LN + GELU + head -> out
    gather_head_kernel<<<WB, 256>>>(hsA, b3, g3, be3, Wh, bh, out, n);
}

// round 15
// speedup vs baseline: 1.0764x; 1.0237x over previous
#include <cuda_runtime.h>
#include <cuda_fp16.h>
#include <cstdint>

// Problem constants (shapes are fixed by the dataset)
#define MAXN 100000
#define MAXE 1600000
#define HDIM 64
#define SCAN_B 1024

// ---------------- scratch (no allocations allowed -> __device__ globals) ----
__device__ int    g_deg[MAXN];                 // zero at load; re-zeroed by scanAC
__device__ float  g_dinv[MAXN];
__device__ int    g_rowstart[MAXN + 1];
__device__ int    g_cursor[MAXN];
__device__ int    g_esrc[MAXE];
__device__ int    g_blocksum[1024];
__device__ int    g_arrive;                    // grid-barrier counter (reset by count)
__device__ __half g_hsA[(size_t)MAXN * HDIM];  // fp16 hs, buffer A
__device__ __half g_hsB[(size_t)MAXN * HDIM];  // fp16 hs, buffer B

// ---------------- helpers ----------------------------------------------------
__device__ __forceinline__ unsigned long long pack2(float x, float y) {
    unsigned long long r;
    asm("mov.b64 %0, {%1,%2};" : "=l"(r) : "f"(x), "f"(y));
    return r;
}
__device__ __forceinline__ unsigned long long add2(unsigned long long a,
                                                   unsigned long long b) {
    unsigned long long d;
    asm("add.rn.f32x2 %0, %1, %2;" : "=l"(d) : "l"(a), "l"(b));
    return d;
}
__device__ __forceinline__ float2 unpack2(unsigned long long v) {
    float2 f;
    asm("mov.b64 {%0,%1}, %2;" : "=f"(f.x), "=f"(f.y) : "l"(v));
    return f;
}
__device__ __forceinline__ unsigned f2tf32(float x) {
    unsigned r;
    asm("cvt.rna.tf32.f32 %0, %1;" : "=r"(r) : "f"(x));
    return r;
}
__device__ __forceinline__ void mma_tf32(float& c0, float& c1, float& c2, float& c3,
                                         unsigned a0, unsigned a1, unsigned a2,
                                         unsigned a3, unsigned b0, unsigned b1) {
    asm("mma.sync.aligned.m16n8k8.row.col.f32.tf32.tf32.f32 "
        "{%0,%1,%2,%3}, {%4,%5,%6,%7}, {%8,%9}, {%0,%1,%2,%3};"
        : "+f"(c0), "+f"(c1), "+f"(c2), "+f"(c3)
        : "r"(a0), "r"(a1), "r"(a2), "r"(a3), "r"(b0), "r"(b1));
}
// add 4 fp16 values (one u64) into 2 packed-f32x2 accumulators
__device__ __forceinline__ void acc_h4(unsigned long long v,
                                       unsigned long long& a01,
                                       unsigned long long& a23) {
    const unsigned lo = (unsigned)v, hi = (unsigned)(v >> 32);
    const float2 f0 = __half22float2(*reinterpret_cast<const __half2*>(&lo));
    const float2 f1 = __half22float2(*reinterpret_cast<const __half2*>(&hi));
    a01 = add2(a01, pack2(f0.x, f0.y));
    a23 = add2(a23, pack2(f1.x, f1.y));
}

// ---------------- CSR build --------------------------------------------------
// 2 edges/thread; also resets the scan grid-barrier counter (stream-ordered
// before scanAC, so no replay hazard).
__global__ void count_deg_kernel(const int* __restrict__ dst, int e) {
    const int i = blockIdx.x * blockDim.x + threadIdx.x;
    if (i == 0) g_arrive = 0;
    const int j = i * 2;
    if (j + 1 < e) {
        const int2 d = ((const int2*)dst)[i];
        atomicAdd(&g_deg[d.x], 1);
        atomicAdd(&g_deg[d.y], 1);
    } else if (j < e) {
        atomicAdd(&g_deg[dst[j]], 1);
    }
}

// Merged scan: per-block exclusive scan of g_deg (+dinv, +deg re-zero), then
// an in-kernel grid barrier (all <=98 blocks co-resident on 148 SMs), then
// each block warp-reduces its prefix of blocksums and writes rowstart+cursor.
__global__ void __launch_bounds__(SCAN_B)
scanAC_kernel(int n, int e) {
    __shared__ int sh[SCAN_B];
    __shared__ int s_off;
    const int t = threadIdx.x;
    const int bid = blockIdx.x;
    const int i = bid * SCAN_B + t;
    const int v = (i < n) ? g_deg[i] : 0;
    if (i < n) {
        g_dinv[i] = rsqrtf((float)v + 1.0f);
        g_deg[i] = 0;                       // ready for next replay
    }
    sh[t] = v;
    __syncthreads();
    int acc = v;
#pragma unroll
    for (int off = 1; off < SCAN_B; off <<= 1) {
        int u = (t >= off) ? sh[t - off] : 0;
        __syncthreads();
        acc += u;
        sh[t] = acc;
        __syncthreads();
    }
    const int local_excl = acc - v;
    if (t == SCAN_B - 1) g_blocksum[bid] = acc;
    __threadfence();
    __syncthreads();                        // blocksum written before arrive
    if (t == 0) {
        atomicAdd(&g_arrive, 1);
        while (*(volatile int*)&g_arrive < gridDim.x) { }
    }
    __syncthreads();                        // all blocksums now visible
    __threadfence();

    if (t < 32) {
        int s = 0;
        for (int j = t; j < bid; j += 32) s += g_blocksum[j];  // <= 4 iters
#pragma unroll
        for (int o = 16; o > 0; o >>= 1)
            s += __shfl_xor_sync(0xffffffffu, s, o);
        if (t == 0) s_off = s;
    }
    __syncthreads();
    if (i < n) {
        const int r = local_excl + s_off;
        g_rowstart[i] = r;
        g_cursor[i]   = r;
    }
    if (i == 0) g_rowstart[n] = e;
}

// 2 edges/thread.
__global__ void place_kernel(const int* __restrict__ src,
                             const int* __restrict__ dst, int e) {
    const int i = blockIdx.x * blockDim.x + threadIdx.x;
    const int j = i * 2;
    if (j + 1 < e) {
        const int2 d = ((const int2*)dst)[i];
        const int2 s = ((const int2*)src)[i];
        const int p0 = atomicAdd(&g_cursor[d.x], 1);
        const int p1 = atomicAdd(&g_cursor[d.y], 1);
        g_esrc[p0] = s.x;
        g_esrc[p1] = s.y;
    } else if (j < e) {
        const int pos = atomicAdd(&g_cursor[dst[j]], 1);
        g_esrc[pos] = src[j];
    }
}

// ---------------- gather core (warp, one node) -> 4 post-GELU floats --------
// lane layout: h = lane>>4 (edge of pair), q = lane&15 (cols 4q..4q+3).
__device__ __forceinline__ void gather_node(const __half* __restrict__ hsin,
                                            int node, int lane, int h, int q,
                                            const float* __restrict__ b,
                                            const float* __restrict__ g,
                                            const float* __restrict__ be,
                                            float& u0, float& u1,
                                            float& u2, float& u3) {
    const int s0 = g_rowstart[node];
    const int s1 = g_rowstart[node + 1];
    const unsigned long long* hsp = (const unsigned long long*)hsin;  // 16/row

    unsigned long long aA01 = 0ull, aA23 = 0ull;
    unsigned long long aB01 = 0ull, aB23 = 0ull;

    for (int e = s0; e < s1; e += 32) {
        const int cnt = min(32, s1 - e);
        const int s = (lane < cnt) ? __ldg(&g_esrc[e + lane]) : 0;
        int i = 0;
        for (; i + 4 <= cnt; i += 4) {           // 2 pairs = 4 edges per iter
            const int sa = __shfl_sync(0xffffffffu, s, i + h);
            const int sb = __shfl_sync(0xffffffffu, s, i + 2 + h);
            const unsigned long long va = __ldg(&hsp[(size_t)sa * 16 + q]);
            const unsigned long long vb = __ldg(&hsp[(size_t)sb * 16 + q]);
            acc_h4(va, aA01, aA23);
            acc_h4(vb, aB01, aB23);
        }
        for (; i < cnt; i += 2) {                // pair tail
            const int idx = i + h;
            const int sa = __shfl_sync(0xffffffffu, s, idx & 31);
            if (idx < cnt)
                acc_h4(__ldg(&hsp[(size_t)sa * 16 + q]), aA01, aA23);
        }
    }

    if (h == 0)                                  // self-loop term, once
        acc_h4(__ldg(&hsp[(size_t)node * 16 + q]), aA01, aA23);

    aA01 = add2(aA01, aB01);
    aA23 = add2(aA23, aB23);
    const float2 p01 = unpack2(aA01);
    const float2 p23 = unpack2(aA23);
    float4 acc = make_float4(p01.x, p01.y, p23.x, p23.y);
    acc.x += __shfl_xor_sync(0xffffffffu, acc.x, 16);
    acc.y += __shfl_xor_sync(0xffffffffu, acc.y, 16);
    acc.z += __shfl_xor_sync(0xffffffffu, acc.z, 16);
    acc.w += __shfl_xor_sync(0xffffffffu, acc.w, 16);

    const float dv = g_dinv[node];
    const float4 b4 = __ldg(&((const float4*)b)[q]);
    float v0 = dv * acc.x + b4.x;
    float v1 = dv * acc.y + b4.y;
    float v2 = dv * acc.z + b4.z;
    float v3 = dv * acc.w + b4.w;

    // LayerNorm over 64 values
    float s  = v0 + v1 + v2 + v3;
    float sq = v0 * v0 + v1 * v1 + v2 * v2 + v3 * v3;
#pragma unroll
    for (int o = 8; o > 0; o >>= 1) {
        s  += __shfl_xor_sync(0xffffffffu, s, o);
        sq += __shfl_xor_sync(0xffffffffu, sq, o);
    }
    const float mu   = s * (1.0f / 64.0f);
    const float var  = sq * (1.0f / 64.0f) - mu * mu;
    const float rstd = rsqrtf(var + 1e-5f);

    const float4 g4  = __ldg(&((const float4*)g)[q]);
    const float4 be4 = __ldg(&((const float4*)be)[q]);
    u0 = (v0 - mu) * rstd * g4.x + be4.x;
    u1 = (v1 - mu) * rstd * g4.y + be4.y;
    u2 = (v2 - mu) * rstd * g4.z + be4.z;
    u3 = (v3 - mu) * rstd * g4.w + be4.w;

    const float k = 0.70710678118654752f;
    u0 = 0.5f * u0 * (1.0f + erff(u0 * k));
    u1 = 0.5f * u1 * (1.0f + erff(u1 * k));
    u2 = 0.5f * u2 * (1.0f + erff(u2 * k));
    u3 = 0.5f * u3 * (1.0f + erff(u3 * k));
}

// ---------------- fused: gather+LN+GELU -> smem tf32 -> MMA W -> fp16 hsout --
// Block = 256 thr / 8 warps / 64 nodes (8 per warp). Double-buffered hs.
__global__ void __launch_bounds__(256)
fused_gather_gemm_kernel(const __half* __restrict__ hsin,
                         const float* __restrict__ b, const float* __restrict__ g,
                         const float* __restrict__ be, const float* __restrict__ Wn,
                         __half* __restrict__ hsout, int n) {
    constexpr int S = HDIM + 4;                  // padded stride (tf32 words)
    __shared__ unsigned Ys[64 * S];              // post-GELU rows (tf32)
    __shared__ unsigned Ws[HDIM * S];            // next-layer W (tf32)

    const int tid  = threadIdx.x;
    const int rb   = blockIdx.x * 64;
    const int warp = tid >> 5;
    const int lane = tid & 31;

    // Stage W (tf32)
    const float4* W4 = (const float4*)Wn;
    for (int idx = tid; idx < HDIM * (HDIM / 4); idx += 256) {
        const int k  = idx / (HDIM / 4);
        const int c4 = idx % (HDIM / 4);
        const float4 v = __ldg(&W4[(size_t)k * (HDIM / 4) + c4]);
        unsigned* d = Ws + k * S + c4 * 4;
        d[0] = f2tf32(v.x); d[1] = f2tf32(v.y);
        d[2] = f2tf32(v.z); d[3] = f2tf32(v.w);
    }

    // Gather phase: warp w handles nodes rb + w*8 .. rb + w*8 + 7
    {
        const int h = lane >> 4;
        const int q = lane & 15;
#pragma unroll 1
        for (int j = 0; j < 8; j++) {
            const int lrow = warp * 8 + j;
            const int node = rb + lrow;
            if (node < n) {
                float u0, u1, u2, u3;
                gather_node(hsin, node, lane, h, q, b, g, be, u0, u1, u2, u3);
                if (h == 0) {
                    unsigned* d = Ys + lrow * S + q * 4;
                    d[0] = f2tf32(u0); d[1] = f2tf32(u1);
                    d[2] = f2tf32(u2); d[3] = f2tf32(u3);
                }
            } else if (h == 0) {
                unsigned* d = Ys + lrow * S + q * 4;
                d[0] = 0u; d[1] = 0u; d[2] = 0u; d[3] = 0u;
            }
        }
    }
    __syncthreads();

    // MMA phase: warp w -> row-group rg = w>>1 (16 rows), col-half ch = w&1
    {
        const int rg = warp >> 1;
        const int ch = warp & 1;
        const int gg = lane >> 2;
        const int t  = lane & 3;

        float c[4][4];
#pragma unroll
        for (int i = 0; i < 4; i++)
#pragma unroll
            for (int j = 0; j < 4; j++) c[i][j] = 0.f;

        const unsigned* Yw = Ys + (rg * 16) * S;
#pragma unroll
        for (int ks = 0; ks < HDIM / 8; ks++) {
            const int kb = ks * 8;
            const unsigned a0 = Yw[gg * S + kb + t];
            const unsigned a1 = Yw[(gg + 8) * S + kb + t];
            const unsigned a2 = Yw[gg * S + kb + t + 4];
            const unsigned a3 = Yw[(gg + 8) * S + kb + t + 4];
#pragma unroll
            for (int nti = 0; nti < 4; nti++) {
                const int nt = ch * 4 + nti;
                const unsigned b0 = Ws[(kb + t) * S + nt * 8 + gg];
                const unsigned b1 = Ws[(kb + t + 4) * S + nt * 8 + gg];
                mma_tf32(c[nti][0], c[nti][1], c[nti][2], c[nti][3],
                         a0, a1, a2, a3, b0, b1);
            }
        }

        const int r0 = rb + rg * 16 + gg;
        const int r1 = r0 + 8;
        const float d0 = __ldg(&g_dinv[min(r0, n - 1)]);
        const float d1 = __ldg(&g_dinv[min(r1, n - 1)]);
        __half2* hs2 = (__half2*)hsout;          // 32 half2 per row
#pragma unroll
        for (int nti = 0; nti < 4; nti++) {
            const int nt = ch * 4 + nti;
            const int cc = nt * 4 + t;
            if (r0 < n)
                hs2[(size_t)r0 * 32 + cc] =
                    __floats2half2_rn(c[nti][0] * d0, c[nti][1] * d0);
            if (r1 < n)
                hs2[(size_t)r1 * 32 + cc] =
                    __floats2half2_rn(c[nti][2] * d1, c[nti][3] * d1);
        }
    }
}

// ---------------- final gather + head: out[node] = gelu(ln(agg)) @ Wh + bh ---
__global__ void __launch_bounds__(256)
gather_head_kernel(const __half* __restrict__ hsin,
                   const float* __restrict__ b, const float* __restrict__ g,
                   const float* __restrict__ be, const float* __restrict__ Wh,
                   const float* __restrict__ bh, float* __restrict__ out, int n) {
    const int warp = (blockIdx.x * blockDim.x + threadIdx.x) >> 5;
    const int lane = threadIdx.x & 31;
    if (warp >= n) return;
    const int h = lane >> 4;
    const int q = lane & 15;

    float u0, u1, u2, u3;
    gather_node(hsin, warp, lane, h, q, b, g, be, u0, u1, u2, u3);

    const float4 w4 = __ldg(&((const float4*)Wh)[q]);
    float p = u0 * w4.x + u1 * w4.y + u2 * w4.z + u3 * w4.w;
#pragma unroll
    for (int o = 8; o > 0; o >>= 1) p += __shfl_xor_sync(0xffffffffu, p, o);
    if (lane == 0) out[warp] = p + __ldg(&bh[0]);
}

// ---------------- layer-1 GEMM (tensor cores): hsA = fp16((X @ W1) * dinv) --
// 64 rows / 256 thr: warps split N (rg = warp>>1 rows, ch = warp&1 col-half).
// smem ~68.6KB -> 3 blocks/SM -> 24 warps (50% occ) for latency hiding.
template <int KDIM>
__global__ void __launch_bounds__(256)
gemm_tf32_kernel(const float* __restrict__ X, const float* __restrict__ W, int n) {
    constexpr int SX = KDIM + 4;
    constexpr int SW = HDIM + 4;
    extern __shared__ unsigned sm[];
    unsigned* Xs = sm;                 // 64 rows x SX
    unsigned* Ws = sm + 64 * SX;       // KDIM rows x SW

    const int tid = threadIdx.x;
    const int rb  = blockIdx.x * 64;

    const float4* X4 = (const float4*)X;
    for (int idx = tid; idx < 64 * (KDIM / 4); idx += 256) {
        const int row = idx / (KDIM / 4);
        const int c4  = idx % (KDIM / 4);
        const int gr  = min(rb + row, n - 1);
        const float4 v = X4[(size_t)gr * (KDIM / 4) + c4];
        unsigned* d = Xs + row * SX + c4 * 4;
        d[0] = f2tf32(v.x); d[1] = f2tf32(v.y);
        d[2] = f2tf32(v.z); d[3] = f2tf32(v.w);
    }
    const float4* W4 = (const float4*)W;
    for (int idx = tid; idx < KDIM * (HDIM / 4); idx += 256) {
        const int k  = idx / (HDIM / 4);
        const int c4 = idx % (HDIM / 4);
        const float4 v = W4[(size_t)k * (HDIM / 4) + c4];
        unsigned* d = Ws + k * SW + c4 * 4;
        d[0] = f2tf32(v.x); d[1] = f2tf32(v.y);
        d[2] = f2tf32(v.z); d[3] = f2tf32(v.w);
    }
    __syncthreads();

    const int warp = tid >> 5;
    const int lane = tid & 31;
    const int rg = warp >> 1;          // 4 row-groups x 16 rows = 64 rows
    const int ch = warp & 1;           // column half (32 cols each)
    const int g = lane >> 2;
    const int t = lane & 3;
    const unsigned* Xw = Xs + (rg * 16) * SX;

    float c[4][4];
#pragma unroll
    for (int nt = 0; nt < 4; nt++)
#pragma unroll
        for (int j = 0; j < 4; j++) c[nt][j] = 0.f;

#pragma unroll
    for (int ks = 0; ks < KDIM / 8; ks++) {
        const int kb = ks * 8;
        const unsigned a0 = Xw[g * SX + kb + t];
        const unsigned a1 = Xw[(g + 8) * SX + kb + t];
        const unsigned a2 = Xw[g * SX + kb + t + 4];
        const unsigned a3 = Xw[(g + 8) * SX + kb + t + 4];
#pragma unroll
        for (int nti = 0; nti < 4; nti++) {
            const int nt = ch * 4 + nti;
            const unsigned b0 = Ws[(kb + t) * SW + nt * 8 + g];
            const unsigned b1 = Ws[(kb + t + 4) * SW + nt * 8 + g];
            mma_tf32(c[nti][0], c[nti][1], c[nti][2], c[nti][3],
                     a0, a1, a2, a3, b0, b1);
        }
    }

    const int r0 = rb + rg * 16 + g;
    const int r1 = r0 + 8;
    const float d0 = __ldg(&g_dinv[min(r0, n - 1)]);
    const float d1 = __ldg(&g_dinv[min(r1, n - 1)]);
    __half2* hs2 = (__half2*)g_hsA;
#pragma unroll
    for (int nti = 0; nti < 4; nti++) {
        const int nt = ch * 4 + nti;
        const int cc = nt * 4 + t;
        if (r0 < n)
            hs2[(size_t)r0 * 32 + cc] =
                __floats2half2_rn(c[nti][0] * d0, c[nti][1] * d0);
        if (r1 < n)
            hs2[(size_t)r1 * 32 + cc] =
                __floats2half2_rn(c[nti][2] * d1, c[nti][3] * d1);
    }
}

// ---------------- launch -----------------------------------------------------
extern "C" void kernel_launch(void* const* d_in, const int* in_sizes, int n_in,
                              void* d_out, int out_size) {
    const float* x   = (const float*)d_in[0];
    const int*   ei  = (const int*)d_in[1];
    const float* W1  = (const float*)d_in[2];
    const float* b1  = (const float*)d_in[3];
    const float* g1  = (const float*)d_in[4];
    const float* be1 = (const float*)d_in[5];
    const float* W2  = (const float*)d_in[6];
    const float* b2  = (const float*)d_in[7];
    const float* g2  = (const float*)d_in[8];
    const float* be2 = (const float*)d_in[9];
    const float* W3  = (const float*)d_in[10];
    const float* b3  = (const float*)d_in[11];
    const float* g3  = (const float*)d_in[12];
    const float* be3 = (const float*)d_in[13];
    const float* Wh  = (const float*)d_in[14];
    const float* bh  = (const float*)d_in[15];
    float* out = (float*)d_out;

    const int n = in_sizes[0] / 128;
    const int e = in_sizes[1] / 2;
    const int* srcs = ei;
    const int* dsts = ei + e;

    const int SM128 = (64 * 132 + 128 * 68) * 4;   // 68608 B dynamic smem

    static __half* hsA = nullptr;
    static __half* hsB = nullptr;
    if (!hsA) {
        cudaGetSymbolAddress((void**)&hsA, g_hsA);
        cudaGetSymbolAddress((void**)&hsB, g_hsB);
        cudaFuncSetAttribute(gemm_tf32_kernel<128>,
                             cudaFuncAttributeMaxDynamicSharedMemorySize, SM128);
    }

    const int E2B = (e / 2 + 255) / 256;       // 2 edges/thread blocks
    const int SB = (n + SCAN_B - 1) / SCAN_B;  // scan blocks (<= 98, co-resident)
    const int GB = (n + 63) / 64;              // gemm1/fused blocks (64 rows)
    const int WB = (n + 7) / 8;                // head blocks (8 warps/block)

    // CSR build: count (also resets grid-barrier ctr) -> merged scan -> place
    count_deg_kernel<<<E2B, 256>>>(dsts, e);
    scanAC_kernel<<<SB, SCAN_B>>>(n, e);       // scan + dinv + cursor, 1 kernel
    place_kernel<<<E2B, 256>>>(srcs, dsts, e);

    // Layer 1 GEMM (IN=128) -> hsA
    gemm_tf32_kernel<128><<<GB, 256, SM128>>>(x, W1, n);
    // Layer 1 gather + LN + GELU + Layer 2 GEMM -> hsB
    fused_gather_gemm_kernel<<<GB, 256>>>(hsA, b1, g1, be1, W2, hsB, n);
    // Layer 2 gather + LN + GELU + Layer 3 GEMM -> hsA
    fused_gather_gemm_kernel<<<GB, 256>>>(hsB, b2, g2, be2, W3, hsA, n);
    // Layer 3 gather + LN + GELU + head -> out
    gather_head_kernel<<<WB, 256>>>(hsA, b3, g3, be3, Wh, bh, out, n);
}

// round 17
// speedup vs baseline: 1.0779x; 1.0013x over previous
#include <cuda_runtime.h>
#include <cuda_fp16.h>
#include <cstdint>

// Problem constants (shapes are fixed by the dataset)
#define MAXN 100000
#define MAXE 1600000
#define HDIM 64
#define SCAN_B 1024

// ---------------- scratch (no allocations allowed -> __device__ globals) ----
__device__ int    g_deg[MAXN];                 // zero at load; re-zeroed by scanAC
__device__ float  g_dinv[MAXN];
__device__ int    g_rowstart[MAXN + 1];
__device__ int    g_cursor[MAXN];
__device__ int    g_esrc[MAXE];
__device__ int    g_blocksum[1024];
__device__ int    g_arrive;                    // grid-barrier counter (reset by count)
__device__ __half g_hsA[(size_t)MAXN * HDIM];  // fp16 hs, buffer A
__device__ __half g_hsB[(size_t)MAXN * HDIM];  // fp16 hs, buffer B

// ---------------- helpers ----------------------------------------------------
__device__ __forceinline__ unsigned long long pack2(float x, float y) {
    unsigned long long r;
    asm("mov.b64 %0, {%1,%2};" : "=l"(r) : "f"(x), "f"(y));
    return r;
}
__device__ __forceinline__ unsigned long long add2(unsigned long long a,
                                                   unsigned long long b) {
    unsigned long long d;
    asm("add.rn.f32x2 %0, %1, %2;" : "=l"(d) : "l"(a), "l"(b));
    return d;
}
__device__ __forceinline__ float2 unpack2(unsigned long long v) {
    float2 f;
    asm("mov.b64 {%0,%1}, %2;" : "=f"(f.x), "=f"(f.y) : "l"(v));
    return f;
}
__device__ __forceinline__ unsigned f2tf32(float x) {
    unsigned r;
    asm("cvt.rna.tf32.f32 %0, %1;" : "=r"(r) : "f"(x));
    return r;
}
// convert float4 -> packed tf32 uint4 (for single STS.128)
__device__ __forceinline__ uint4 f4_to_tf32(float4 v) {
    uint4 u;
    u.x = f2tf32(v.x); u.y = f2tf32(v.y);
    u.z = f2tf32(v.z); u.w = f2tf32(v.w);
    return u;
}
__device__ __forceinline__ void mma_tf32(float& c0, float& c1, float& c2, float& c3,
                                         unsigned a0, unsigned a1, unsigned a2,
                                         unsigned a3, unsigned b0, unsigned b1) {
    asm("mma.sync.aligned.m16n8k8.row.col.f32.tf32.tf32.f32 "
        "{%0,%1,%2,%3}, {%4,%5,%6,%7}, {%8,%9}, {%0,%1,%2,%3};"
        : "+f"(c0), "+f"(c1), "+f"(c2), "+f"(c3)
        : "r"(a0), "r"(a1), "r"(a2), "r"(a3), "r"(b0), "r"(b1));
}
// add 4 fp16 values (one u64) into 2 packed-f32x2 accumulators
__device__ __forceinline__ void acc_h4(unsigned long long v,
                                       unsigned long long& a01,
                                       unsigned long long& a23) {
    const unsigned lo = (unsigned)v, hi = (unsigned)(v >> 32);
    const float2 f0 = __half22float2(*reinterpret_cast<const __half2*>(&lo));
    const float2 f1 = __half22float2(*reinterpret_cast<const __half2*>(&hi));
    a01 = add2(a01, pack2(f0.x, f0.y));
    a23 = add2(a23, pack2(f1.x, f1.y));
}

// ---------------- CSR build --------------------------------------------------
// 2 edges/thread; also resets the scan grid-barrier counter (stream-ordered
// before scanAC, so no replay hazard).
__global__ void count_deg_kernel(const int* __restrict__ dst, int e) {
    const int i = blockIdx.x * blockDim.x + threadIdx.x;
    if (i == 0) g_arrive = 0;
    const int j = i * 2;
    if (j + 1 < e) {
        const int2 d = ((const int2*)dst)[i];
        atomicAdd(&g_deg[d.x], 1);
        atomicAdd(&g_deg[d.y], 1);
    } else if (j < e) {
        atomicAdd(&g_deg[dst[j]], 1);
    }
}

// Merged scan: per-block exclusive scan of g_deg (+dinv, +deg re-zero), then
// an in-kernel grid barrier (all <=98 blocks co-resident on 148 SMs), then
// each block warp-reduces its prefix of blocksums and writes rowstart+cursor.
__global__ void __launch_bounds__(SCAN_B)
scanAC_kernel(int n, int e) {
    __shared__ int sh[SCAN_B];
    __shared__ int s_off;
    const int t = threadIdx.x;
    const int bid = blockIdx.x;
    const int i = bid * SCAN_B + t;
    const int v = (i < n) ? g_deg[i] : 0;
    if (i < n) {
        g_dinv[i] = rsqrtf((float)v + 1.0f);
        g_deg[i] = 0;                       // ready for next replay
    }
    sh[t] = v;
    __syncthreads();
    int acc = v;
#pragma unroll
    for (int off = 1; off < SCAN_B; off <<= 1) {
        int u = (t >= off) ? sh[t - off] : 0;
        __syncthreads();
        acc += u;
        sh[t] = acc;
        __syncthreads();
    }
    const int local_excl = acc - v;
    if (t == SCAN_B - 1) g_blocksum[bid] = acc;
    __threadfence();
    __syncthreads();                        // blocksum written before arrive
    if (t == 0) {
        atomicAdd(&g_arrive, 1);
        while (*(volatile int*)&g_arrive < gridDim.x) { }
    }
    __syncthreads();                        // all blocksums now visible
    __threadfence();

    if (t < 32) {
        int s = 0;
        for (int j = t; j < bid; j += 32) s += g_blocksum[j];  // <= 4 iters
#pragma unroll
        for (int o = 16; o > 0; o >>= 1)
            s += __shfl_xor_sync(0xffffffffu, s, o);
        if (t == 0) s_off = s;
    }
    __syncthreads();
    if (i < n) {
        const int r = local_excl + s_off;
        g_rowstart[i] = r;
        g_cursor[i]   = r;
    }
    if (i == 0) g_rowstart[n] = e;
}

// 2 edges/thread.
__global__ void place_kernel(const int* __restrict__ src,
                             const int* __restrict__ dst, int e) {
    const int i = blockIdx.x * blockDim.x + threadIdx.x;
    const int j = i * 2;
    if (j + 1 < e) {
        const int2 d = ((const int2*)dst)[i];
        const int2 s = ((const int2*)src)[i];
        const int p0 = atomicAdd(&g_cursor[d.x], 1);
        const int p1 = atomicAdd(&g_cursor[d.y], 1);
        g_esrc[p0] = s.x;
        g_esrc[p1] = s.y;
    } else if (j < e) {
        const int pos = atomicAdd(&g_cursor[dst[j]], 1);
        g_esrc[pos] = src[j];
    }
}

// ---------------- gather core (warp, one node) -> 4 post-GELU floats --------
// lane layout: h = lane>>4 (edge of pair), q = lane&15 (cols 4q..4q+3).
__device__ __forceinline__ void gather_node(const __half* __restrict__ hsin,
                                            int node, int lane, int h, int q,
                                            const float* __restrict__ b,
                                            const float* __restrict__ g,
                                            const float* __restrict__ be,
                                            float& u0, float& u1,
                                            float& u2, float& u3) {
    const int s0 = g_rowstart[node];
    const int s1 = g_rowstart[node + 1];
    const unsigned long long* hsp = (const unsigned long long*)hsin;  // 16/row

    unsigned long long aA01 = 0ull, aA23 = 0ull;
    unsigned long long aB01 = 0ull, aB23 = 0ull;

    for (int e = s0; e < s1; e += 32) {
        const int cnt = min(32, s1 - e);
        const int s = (lane < cnt) ? __ldg(&g_esrc[e + lane]) : 0;
        int i = 0;
        for (; i + 4 <= cnt; i += 4) {           // 2 pairs = 4 edges per iter
            const int sa = __shfl_sync(0xffffffffu, s, i + h);
            const int sb = __shfl_sync(0xffffffffu, s, i + 2 + h);
            const unsigned long long va = __ldg(&hsp[(size_t)sa * 16 + q]);
            const unsigned long long vb = __ldg(&hsp[(size_t)sb * 16 + q]);
            acc_h4(va, aA01, aA23);
            acc_h4(vb, aB01, aB23);
        }
        for (; i < cnt; i += 2) {                // pair tail
            const int idx = i + h;
            const int sa = __shfl_sync(0xffffffffu, s, idx & 31);
            if (idx < cnt)
                acc_h4(__ldg(&hsp[(size_t)sa * 16 + q]), aA01, aA23);
        }
    }

    if (h == 0)                                  // self-loop term, once
        acc_h4(__ldg(&hsp[(size_t)node * 16 + q]), aA01, aA23);

    aA01 = add2(aA01, aB01);
    aA23 = add2(aA23, aB23);
    const float2 p01 = unpack2(aA01);
    const float2 p23 = unpack2(aA23);
    float4 acc = make_float4(p01.x, p01.y, p23.x, p23.y);
    acc.x += __shfl_xor_sync(0xffffffffu, acc.x, 16);
    acc.y += __shfl_xor_sync(0xffffffffu, acc.y, 16);
    acc.z += __shfl_xor_sync(0xffffffffu, acc.z, 16);
    acc.w += __shfl_xor_sync(0xffffffffu, acc.w, 16);

    const float dv = g_dinv[node];
    const float4 b4 = __ldg(&((const float4*)b)[q]);
    float v0 = dv * acc.x + b4.x;
    float v1 = dv * acc.y + b4.y;
    float v2 = dv * acc.z + b4.z;
    float v3 = dv * acc.w + b4.w;

    // LayerNorm over 64 values
    float s  = v0 + v1 + v2 + v3;
    float sq = v0 * v0 + v1 * v1 + v2 * v2 + v3 * v3;
#pragma unroll
    for (int o = 8; o > 0; o >>= 1) {
        s  += __shfl_xor_sync(0xffffffffu, s, o);
        sq += __shfl_xor_sync(0xffffffffu, sq, o);
    }
    const float mu   = s * (1.0f / 64.0f);
    const float var  = sq * (1.0f / 64.0f) - mu * mu;
    const float rstd = rsqrtf(var + 1e-5f);

    const float4 g4  = __ldg(&((const float4*)g)[q]);
    const float4 be4 = __ldg(&((const float4*)be)[q]);
    u0 = (v0 - mu) * rstd * g4.x + be4.x;
    u1 = (v1 - mu) * rstd * g4.y + be4.y;
    u2 = (v2 - mu) * rstd * g4.z + be4.z;
    u3 = (v3 - mu) * rstd * g4.w + be4.w;

    const float k = 0.70710678118654752f;
    u0 = 0.5f * u0 * (1.0f + erff(u0 * k));
    u1 = 0.5f * u1 * (1.0f + erff(u1 * k));
    u2 = 0.5f * u2 * (1.0f + erff(u2 * k));
    u3 = 0.5f * u3 * (1.0f + erff(u3 * k));
}

// ---------------- fused: gather+LN+GELU -> smem tf32 -> MMA W -> fp16 hsout --
// Block = 256 thr / 8 warps / 64 nodes (8 per warp). Double-buffered hs.
__global__ void __launch_bounds__(256)
fused_gather_gemm_kernel(const __half* __restrict__ hsin,
                         const float* __restrict__ b, const float* __restrict__ g,
                         const float* __restrict__ be, const float* __restrict__ Wn,
                         __half* __restrict__ hsout, int n) {
    constexpr int S = HDIM + 4;                  // padded stride (tf32 words)
    __shared__ unsigned Ys[64 * S];              // post-GELU rows (tf32)
    __shared__ unsigned Ws[HDIM * S];            // next-layer W (tf32)

    const int tid  = threadIdx.x;
    const int rb   = blockIdx.x * 64;
    const int warp = tid >> 5;
    const int lane = tid & 31;

    // Stage W (tf32), packed 16B stores (S*4 = 272B and q*16B are 16B-aligned)
    const float4* W4 = (const float4*)Wn;
    for (int idx = tid; idx < HDIM * (HDIM / 4); idx += 256) {
        const int k  = idx / (HDIM / 4);
        const int c4 = idx % (HDIM / 4);
        const float4 v = __ldg(&W4[(size_t)k * (HDIM / 4) + c4]);
        *reinterpret_cast<uint4*>(Ws + k * S + c4 * 4) = f4_to_tf32(v);
    }

    // Gather phase: warp w handles nodes rb + w*8 .. rb + w*8 + 7
    {
        const int h = lane >> 4;
        const int q = lane & 15;
#pragma unroll 1
        for (int j = 0; j < 8; j++) {
            const int lrow = warp * 8 + j;
            const int node = rb + lrow;
            if (node < n) {
                float u0, u1, u2, u3;
                gather_node(hsin, node, lane, h, q, b, g, be, u0, u1, u2, u3);
                if (h == 0) {
                    *reinterpret_cast<uint4*>(Ys + lrow * S + q * 4) =
                        f4_to_tf32(make_float4(u0, u1, u2, u3));
                }
            } else if (h == 0) {
                *reinterpret_cast<uint4*>(Ys + lrow * S + q * 4) =
                    make_uint4(0u, 0u, 0u, 0u);
            }
        }
    }
    __syncthreads();

    // MMA phase: warp w -> row-group rg = w>>1 (16 rows), col-half ch = w&1
    {
        const int rg = warp >> 1;
        const int ch = warp & 1;
        const int gg = lane >> 2;
        const int t  = lane & 3;

        float c[4][4];
#pragma unroll
        for (int i = 0; i < 4; i++)
#pragma unroll
            for (int j = 0; j < 4; j++) c[i][j] = 0.f;

        const unsigned* Yw = Ys + (rg * 16) * S;
#pragma unroll
        for (int ks = 0; ks < HDIM / 8; ks++) {
            const int kb = ks * 8;
            const unsigned a0 = Yw[gg * S + kb + t];
            const unsigned a1 = Yw[(gg + 8) * S + kb + t];
            const unsigned a2 = Yw[gg * S + kb + t + 4];
            const unsigned a3 = Yw[(gg + 8) * S + kb + t + 4];
#pragma unroll
            for (int nti = 0; nti < 4; nti++) {
                const int nt = ch * 4 + nti;
                const unsigned b0 = Ws[(kb + t) * S + nt * 8 + gg];
                const unsigned b1 = Ws[(kb + t + 4) * S + nt * 8 + gg];
                mma_tf32(c[nti][0], c[nti][1], c[nti][2], c[nti][3],
                         a0, a1, a2, a3, b0, b1);
            }
        }

        const int r0 = rb + rg * 16 + gg;
        const int r1 = r0 + 8;
        const float d0 = __ldg(&g_dinv[min(r0, n - 1)]);
        const float d1 = __ldg(&g_dinv[min(r1, n - 1)]);
        __half2* hs2 = (__half2*)hsout;          // 32 half2 per row
#pragma unroll
        for (int nti = 0; nti < 4; nti++) {
            const int nt = ch * 4 + nti;
            const int cc = nt * 4 + t;
            if (r0 < n)
                hs2[(size_t)r0 * 32 + cc] =
                    __floats2half2_rn(c[nti][0] * d0, c[nti][1] * d0);
            if (r1 < n)
                hs2[(size_t)r1 * 32 + cc] =
                    __floats2half2_rn(c[nti][2] * d1, c[nti][3] * d1);
        }
    }
}

// ---------------- final gather + head: out[node] = gelu(ln(agg)) @ Wh + bh ---
__global__ void __launch_bounds__(256)
gather_head_kernel(const __half* __restrict__ hsin,
                   const float* __restrict__ b, const float* __restrict__ g,
                   const float* __restrict__ be, const float* __restrict__ Wh,
                   const float* __restrict__ bh, float* __restrict__ out, int n) {
    const int warp = (blockIdx.x * blockDim.x + threadIdx.x) >> 5;
    const int lane = threadIdx.x & 31;
    if (warp >= n) return;
    const int h = lane >> 4;
    const int q = lane & 15;

    float u0, u1, u2, u3;
    gather_node(hsin, warp, lane, h, q, b, g, be, u0, u1, u2, u3);

    const float4 w4 = __ldg(&((const float4*)Wh)[q]);
    float p = u0 * w4.x + u1 * w4.y + u2 * w4.z + u3 * w4.w;
#pragma unroll
    for (int o = 8; o > 0; o >>= 1) p += __shfl_xor_sync(0xffffffffu, p, o);
    if (lane == 0) out[warp] = p + __ldg(&bh[0]);
}

// ---------------- layer-1 GEMM (tensor cores): hsA = fp16((X @ W1) * dinv) --
// 64 rows / 256 thr: warps split N (rg = warp>>1 rows, ch = warp&1 col-half).
// smem ~68.6KB -> 3 blocks/SM -> 24 warps for latency hiding.
// Staging uses packed 16B STS (SX*4=528B, SW*4=272B both 16B-multiples).
template <int KDIM>
__global__ void __launch_bounds__(256)
gemm_tf32_kernel(const float* __restrict__ X, const float* __restrict__ W, int n) {
    constexpr int SX = KDIM + 4;
    constexpr int SW = HDIM + 4;
    extern __shared__ unsigned sm[];
    unsigned* Xs = sm;                 // 64 rows x SX
    unsigned* Ws = sm + 64 * SX;       // KDIM rows x SW

    const int tid = threadIdx.x;
    const int rb  = blockIdx.x * 64;

    const float4* X4 = (const float4*)X;
    for (int idx = tid; idx < 64 * (KDIM / 4); idx += 256) {
        const int row = idx / (KDIM / 4);
        const int c4  = idx % (KDIM / 4);
        const int gr  = min(rb + row, n - 1);
        const float4 v = X4[(size_t)gr * (KDIM / 4) + c4];
        *reinterpret_cast<uint4*>(Xs + row * SX + c4 * 4) = f4_to_tf32(v);
    }
    const float4* W4 = (const float4*)W;
    for (int idx = tid; idx < KDIM * (HDIM / 4); idx += 256) {
        const int k  = idx / (HDIM / 4);
        const int c4 = idx % (HDIM / 4);
        const float4 v = W4[(size_t)k * (HDIM / 4) + c4];
        *reinterpret_cast<uint4*>(Ws + k * SW + c4 * 4) = f4_to_tf32(v);
    }
    __syncthreads();

    const int warp = tid >> 5;
    const int lane = tid & 31;
    const int rg = warp >> 1;          // 4 row-groups x 16 rows = 64 rows
    const int ch = warp & 1;           // column half (32 cols each)
    const int g = lane >> 2;
    const int t = lane & 3;
    const unsigned* Xw = Xs + (rg * 16) * SX;

    float c[4][4];
#pragma unroll
    for (int nt = 0; nt < 4; nt++)
#pragma unroll
        for (int j = 0; j < 4; j++) c[nt][j] = 0.f;

#pragma unroll
    for (int ks = 0; ks < KDIM / 8; ks++) {
        const int kb = ks * 8;
        const unsigned a0 = Xw[g * SX + kb + t];
        const unsigned a1 = Xw[(g + 8) * SX + kb + t];
        const unsigned a2 = Xw[g * SX + kb + t + 4];
        const unsigned a3 = Xw[(g + 8) * SX + kb + t + 4];
#pragma unroll
        for (int nti = 0; nti < 4; nti++) {
            const int nt = ch * 4 + nti;
            const unsigned b0 = Ws[(kb + t) * SW + nt * 8 + g];
            const unsigned b1 = Ws[(kb + t + 4) * SW + nt * 8 + g];
            mma_tf32(c[nti][0], c[nti][1], c[nti][2], c[nti][3],
                     a0, a1, a2, a3, b0, b1);
        }
    }

    const int r0 = rb + rg * 16 + g;
    const int r1 = r0 + 8;
    const float d0 = __ldg(&g_dinv[min(r0, n - 1)]);
    const float d1 = __ldg(&g_dinv[min(r1, n - 1)]);
    __half2* hs2 = (__half2*)g_hsA;
#pragma unroll
    for (int nti = 0; nti < 4; nti++) {
        const int nt = ch * 4 + nti;
        const int cc = nt * 4 + t;
        if (r0 < n)
            hs2[(size_t)r0 * 32 + cc] =
                __floats2half2_rn(c[nti][0] * d0, c[nti][1] * d0);
        if (r1 < n)
            hs2[(size_t)r1 * 32 + cc] =
                __floats2half2_rn(c[nti][2] * d1, c[nti][3] * d1);
    }
}

// ---------------- launch -----------------------------------------------------
extern "C" void kernel_launch(void* const* d_in, const int* in_sizes, int n_in,
                              void* d_out, int out_size) {
    const float* x   = (const float*)d_in[0];
    const int*   ei  = (const int*)d_in[1];
    const float* W1  = (const float*)d_in[2];
    const float* b1  = (const float*)d_in[3];
    const float* g1  = (const float*)d_in[4];
    const float* be1 = (const float*)d_in[5];
    const float* W2  = (const float*)d_in[6];
    const float* b2  = (const float*)d_in[7];
    const float* g2  = (const float*)d_in[8];
    const float* be2 = (const float*)d_in[9];
    const float* W3  = (const float*)d_in[10];
    const float* b3  = (const float*)d_in[11];
    const float* g3  = (const float*)d_in[12];
    const float* be3 = (const float*)d_in[13];
    const float* Wh  = (const float*)d_in[14];
    const float* bh  = (const float*)d_in[15];
    float* out = (float*)d_out;

    const int n = in_sizes[0] / 128;
    const int e = in_sizes[1] / 2;
    const int* srcs = ei;
    const int* dsts = ei + e;

    const int SM128 = (64 * 132 + 128 * 68) * 4;   // 68608 B dynamic smem

    static __half* hsA = nullptr;
    static __half* hsB = nullptr;
    if (!hsA) {
        cudaGetSymbolAddress((void**)&hsA, g_hsA);
        cudaGetSymbolAddress((void**)&hsB, g_hsB);
        cudaFuncSetAttribute(gemm_tf32_kernel<128>,
                             cudaFuncAttributeMaxDynamicSharedMemorySize, SM128);
    }

    const int E2B = (e / 2 + 255) / 256;       // 2 edges/thread blocks
    const int SB = (n + SCAN_B - 1) / SCAN_B;  // scan blocks (<= 98, co-resident)
    const int GB = (n + 63) / 64;              // gemm1/fused blocks (64 rows)
    const int WB = (n + 7) / 8;                // head blocks (8 warps/block)

    // CSR build: count (also resets grid-barrier ctr) -> merged scan -> place
    count_deg_kernel<<<E2B, 256>>>(dsts, e);
    scanAC_kernel<<<SB, SCAN_B>>>(n, e);       // scan + dinv + cursor, 1 kernel
    place_kernel<<<E2B, 256>>>(srcs, dsts, e);

    // Layer 1 GEMM (IN=128) -> hsA
    gemm_tf32_kernel<128><<<GB, 256, SM128>>>(x, W1, n);
    // Layer 1 gather + LN + GELU + Layer 2 GEMM -> hsB
    fused_gather_gemm_kernel<<<GB, 256>>>(hsA, b1, g1, be1, W2, hsB, n);
    // Layer 2 gather + LN + GELU + Layer 3 GEMM -> hsA
    fused_gather_gemm_kernel<<<GB, 256>>>(hsB, b2, g2, be2, W3, hsA, n);
    // Layer 3 gather + LN + GELU + head -> out
    gather_head_kernel<<<WB, 256>>>(hsA, b3, g3, be3, Wh, bh, out, n);
}